// round 1
// baseline (speedup 1.0000x reference)
#include <cuda_runtime.h>
#include <math.h>

#define B_   4096
#define M_   16
#define C_   1000
#define EMB_ 100
#define K_   1000
#define NL_  4

// output layout (tuple-order concat, fp32)
#define O_POST  0
#define O_CHILD 4096000
#define O_CONF  4096001
#define O_ENS   4096002
#define O_WMS   4096003
#define O_TC    4161539

// scratch
__device__ float g_emb[M_ * EMB_];
__device__ float g_wm [B_ * M_];
__device__ float g_pw [B_ * M_];
__device__ float g_wms[B_ * M_];
__device__ float g_part[B_ * 4];

// ---------------------------------------------------------------------------
// Kernel A: emb[m][e] = relu(model_emb[m,:] . w2[e,:] + b2[e])
// ---------------------------------------------------------------------------
__global__ void k_emb(const float* __restrict__ me, const float* __restrict__ w2,
                      const float* __restrict__ b2) {
    int m = blockIdx.x;
    int wid = threadIdx.x >> 5, lane = threadIdx.x & 31;
    const float* mer = me + m * K_;
    for (int e = wid; e < EMB_; e += 8) {
        const float* w2r = w2 + e * K_;
        float acc = 0.f;
        #pragma unroll
        for (int i = 0; i < 32; i++) {
            int k = lane + (i << 5);
            if (k < K_) acc += mer[k] * w2r[k];
        }
        #pragma unroll
        for (int off = 16; off; off >>= 1)
            acc += __shfl_xor_sync(0xffffffffu, acc, off);
        if (lane == 0) g_emb[m * EMB_ + e] = fmaxf(acc + b2[e], 0.f);
    }
}

// ---------------------------------------------------------------------------
// Kernel B: routing weights for 16 rows per block (256 blocks).
// Each warp owns 2 rows; x held in registers; w1 staged via smem (CE=9 cols).
// ---------------------------------------------------------------------------
#define CE_ 9

__global__ __launch_bounds__(256, 1)
void k_route(const float* __restrict__ x_in, const float* __restrict__ w1,
             const float* __restrict__ b1, const float* __restrict__ w3,
             const float* __restrict__ b3, float* __restrict__ out) {
    __shared__ float w_s[CE_ * 1024];     // 36.9 KB
    __shared__ float emb_s[M_ * EMB_];    // 6.4 KB
    __shared__ float b1_s[EMB_];
    __shared__ float w3_s[M_ * M_];
    __shared__ float b3_s[M_];
    __shared__ float wtmp[16 * M_];

    int tid = threadIdx.x;
    int wid = tid >> 5, lane = tid & 31;
    int base = blockIdx.x * 16;

    for (int i = tid; i < M_ * EMB_; i += 256) emb_s[i] = g_emb[i];
    if (tid < EMB_) b1_s[tid] = b1[tid];
    if (tid < M_ * M_) w3_s[tid] = w3[tid];
    if (tid < M_) b3_s[tid] = b3[tid];

    // preload x for my 2 rows into registers
    int r0 = base + 2 * wid;
    const float* xr0 = x_in + (size_t)r0 * K_;
    const float* xr1 = xr0 + K_;
    float x0[32], x1[32];
    #pragma unroll
    for (int i = 0; i < 32; i++) {
        int k = lane + (i << 5);
        x0[i] = (k < K_) ? xr0[k] : 0.f;
        x1[i] = (k < K_) ? xr1[k] : 0.f;
    }

    float score = 0.f;   // lane (r = lane>>4, m = lane&15)
    int m = lane & 15, rr = lane >> 4;

    for (int ec = 0; ec < EMB_; ec += CE_) {
        __syncthreads();
        for (int idx = tid; idx < CE_ * 1024; idx += 256) {
            int e = idx >> 10, col = idx & 1023;
            int eg = ec + e;
            w_s[idx] = (col < K_ && eg < EMB_) ? w1[eg * K_ + col] : 0.f;
        }
        __syncthreads();
        int elim = min(CE_, EMB_ - ec);
        for (int el = 0; el < elim; el++) {
            const float* wrow = &w_s[el << 10];
            float a0 = 0.f, a1 = 0.f;
            #pragma unroll
            for (int i = 0; i < 32; i++) {
                float w = wrow[lane + (i << 5)];
                a0 += w * x0[i];
                a1 += w * x1[i];
            }
            #pragma unroll
            for (int off = 16; off; off >>= 1) {
                a0 += __shfl_xor_sync(0xffffffffu, a0, off);
                a1 += __shfl_xor_sync(0xffffffffu, a1, off);
            }
            int eg = ec + el;
            float bb = b1_s[eg];
            float f0 = fmaxf(a0 + bb, 0.f);
            float f1 = fmaxf(a1 + bb, 0.f);
            float f = rr ? f1 : f0;
            score += f * emb_s[m * EMB_ + eg];
        }
    }

    // weights = softplus(scores @ w3^T + b3)
    float acc = b3_s[m];
    #pragma unroll
    for (int m2 = 0; m2 < M_; m2++) {
        float sc = __shfl_sync(0xffffffffu, score, (lane & 16) | m2);
        acc += w3_s[m * M_ + m2] * sc;
    }
    float wgt = (acc > 0.f) ? acc + log1pf(expf(-acc)) : log1pf(expf(acc));

    // L1 normalize over 16 lanes of the same row
    float rs = wgt;
    #pragma unroll
    for (int off = 8; off; off >>= 1) rs += __shfl_xor_sync(0xffffffffu, rs, off);
    float wmval = wgt / fmaxf(rs, 1e-12f);

    // softmax over row
    float mx = wmval;
    #pragma unroll
    for (int off = 8; off; off >>= 1) mx = fmaxf(mx, __shfl_xor_sync(0xffffffffu, mx, off));
    float ex = expf(wmval - mx);
    float es = ex;
    #pragma unroll
    for (int off = 8; off; off >>= 1) es += __shfl_xor_sync(0xffffffffu, es, off);
    float wms = ex / es;

    int row = base + 2 * wid + rr;
    g_wm [row * M_ + m] = wmval;
    g_wms[row * M_ + m] = wms;
    out[O_WMS + row * M_ + m] = wms;
    wtmp[(2 * wid + rr) * M_ + m] = wmval;
    __syncthreads();

    // top-4 + renormalize (one thread per row)
    if (tid < 16) {
        float v[M_], pw[M_];
        #pragma unroll
        for (int j = 0; j < M_; j++) { v[j] = wtmp[tid * M_ + j]; pw[j] = 0.f; }
        float ssum = 0.f;
        #pragma unroll
        for (int it = 0; it < NL_; it++) {
            int bi = 0; float bv = -1.f;
            #pragma unroll
            for (int j = 0; j < M_; j++) if (v[j] > bv) { bv = v[j]; bi = j; }
            pw[bi] = bv; ssum += bv; v[bi] = -2.f;
        }
        float inv = 1.f / fmaxf(ssum, 1e-12f);
        int row2 = base + tid;
        #pragma unroll
        for (int j = 0; j < M_; j++) g_pw[row2 * M_ + j] = pw[j] * inv;
    }
}

// ---------------------------------------------------------------------------
// Kernel C: the 262 MB streamer. One block per batch row.
// ---------------------------------------------------------------------------
__global__ __launch_bounds__(256)
void k_main(const float* __restrict__ y, const int* __restrict__ labels,
            float* __restrict__ out) {
    int b = blockIdx.x, tid = threadIdx.x;
    __shared__ float wm_sh[M_], pw_sh[M_], ylab[M_];
    __shared__ float red[17][8];
    __shared__ float fin[17];
    __shared__ float slab_sh;

    if (tid < M_) { wm_sh[tid] = g_wm[b * M_ + tid]; pw_sh[tid] = g_pw[b * M_ + tid]; }
    __syncthreads();

    int lab = labels[b];
    float wl[M_], pl[M_];
    #pragma unroll
    for (int m = 0; m < M_; m++) { wl[m] = wm_sh[m]; pl[m] = pw_sh[m]; }

    float sume[M_];
    #pragma unroll
    for (int m = 0; m < M_; m++) sume[m] = 0.f;
    float sumS = 0.f;

    if (tid < 250) {
        const float4* yb = (const float4*)(y + (size_t)b * (M_ * C_));
        float s0 = 0, s1 = 0, s2 = 0, s3 = 0;
        float p0 = 0, p1 = 0, p2 = 0, p3 = 0;
        int labq = lab >> 2, labr = lab & 3;
        bool own = (tid == labq);
        #pragma unroll
        for (int m = 0; m < M_; m++) {
            float4 v = yb[m * 250 + tid];
            s0 += wl[m] * v.x; s1 += wl[m] * v.y; s2 += wl[m] * v.z; s3 += wl[m] * v.w;
            p0 += pl[m] * v.x; p1 += pl[m] * v.y; p2 += pl[m] * v.z; p3 += pl[m] * v.w;
            sume[m] += __expf(v.x) + __expf(v.y) + __expf(v.z) + __expf(v.w);
            if (own) ylab[m] = (labr == 0) ? v.x : (labr == 1) ? v.y : (labr == 2) ? v.z : v.w;
        }
        float4* ob = (float4*)(out + O_POST + (size_t)b * C_);
        ob[tid] = make_float4(p0, p1, p2, p3);
        sumS = __expf(s0) + __expf(s1) + __expf(s2) + __expf(s3);
        if (own) slab_sh = (labr == 0) ? s0 : (labr == 1) ? s1 : (labr == 2) ? s2 : s3;
    }

    // block reduce 17 sums
    int lane = tid & 31, wid = tid >> 5;
    #pragma unroll
    for (int j = 0; j < 17; j++) {
        float v = (j < M_) ? sume[j] : sumS;
        #pragma unroll
        for (int off = 16; off; off >>= 1) v += __shfl_xor_sync(0xffffffffu, v, off);
        if (lane == 0) red[j][wid] = v;
    }
    __syncthreads();
    if (tid < 17) {
        float v = 0.f;
        #pragma unroll
        for (int w = 0; w < 8; w++) v += red[tid][w];
        fin[tid] = v;
    }
    __syncthreads();

    if (tid == 0) {
        float epl[M_], tcp[M_];
        #pragma unroll
        for (int m = 0; m < M_; m++) {
            float lse = logf(fin[m]);
            epl[m] = lse - ylab[m];
            tcp[m] = __expf(ylab[m] - lse);
        }
        // true_confs = softmax(tcp)
        float mx = tcp[0];
        #pragma unroll
        for (int m = 1; m < M_; m++) mx = fmaxf(mx, tcp[m]);
        float den = 0.f; float tc[M_];
        #pragma unroll
        for (int m = 0; m < M_; m++) { tc[m] = __expf(tcp[m] - mx); den += tc[m]; }
        #pragma unroll
        for (int m = 0; m < M_; m++) { tc[m] /= den; out[O_TC + b * M_ + m] = tc[m]; }
        // t = softmax(true_confs)
        float mx2 = tc[0];
        #pragma unroll
        for (int m = 1; m < M_; m++) mx2 = fmaxf(mx2, tc[m]);
        float den2 = 0.f; float tt[M_];
        #pragma unroll
        for (int m = 0; m < M_; m++) { tt[m] = __expf(tc[m] - mx2); den2 += tt[m]; }
        float child = 0.f, conf = 0.f;
        #pragma unroll
        for (int m = 0; m < M_; m++) {
            float t = tt[m] / den2;
            float x = g_wms[b * M_ + m];
            conf  += x - x * t + log1pf(expf(-x));
            child += epl[m] * x;
        }
        float ens = logf(fin[16]) - slab_sh;
        g_part[b * 4 + 0] = child;
        g_part[b * 4 + 1] = conf;
        g_part[b * 4 + 2] = ens;
    }
}

// ---------------------------------------------------------------------------
// Kernel D: deterministic final reduce of the 3 scalar losses
// ---------------------------------------------------------------------------
__global__ void k_final(float* __restrict__ out) {
    __shared__ float r0[256], r1[256], r2[256];
    int t = threadIdx.x;
    float a = 0.f, b = 0.f, c = 0.f;
    for (int i = t; i < B_; i += 256) {
        a += g_part[i * 4 + 0];
        b += g_part[i * 4 + 1];
        c += g_part[i * 4 + 2];
    }
    r0[t] = a; r1[t] = b; r2[t] = c;
    __syncthreads();
    for (int s = 128; s; s >>= 1) {
        if (t < s) { r0[t] += r0[t + s]; r1[t] += r1[t + s]; r2[t] += r2[t + s]; }
        __syncthreads();
    }
    if (t == 0) {
        out[O_CHILD] = r0[0] / (float)(B_ * M_);
        out[O_CONF]  = r1[0] / (float)(B_ * M_);
        out[O_ENS]   = r2[0] / (float)B_;
    }
}

// ---------------------------------------------------------------------------
extern "C" void kernel_launch(void* const* d_in, const int* in_sizes, int n_in,
                              void* d_out, int out_size) {
    const float* x_in  = (const float*)d_in[0];
    const float* y     = (const float*)d_in[1];
    const int*   labs  = (const int*)  d_in[2];
    const float* memb  = (const float*)d_in[3];
    const float* w1    = (const float*)d_in[4];
    const float* b1    = (const float*)d_in[5];
    const float* w2    = (const float*)d_in[6];
    const float* b2    = (const float*)d_in[7];
    const float* w3    = (const float*)d_in[8];
    const float* b3    = (const float*)d_in[9];
    float* out = (float*)d_out;

    k_emb  <<<M_, 256>>>(memb, w2, b2);
    k_route<<<B_ / 16, 256>>>(x_in, w1, b1, w3, b3, out);
    k_main <<<B_, 256>>>(y, labs, out);
    k_final<<<1, 256>>>(out);
}

// round 2
// speedup vs baseline: 1.6229x; 1.6229x over previous
#include <cuda_runtime.h>
#include <math.h>

#define B_   4096
#define M_   16
#define C_   1000
#define EMB_ 100
#define K_   1000
#define NL_  4

// output layout (tuple-order concat, fp32)
#define O_POST  0
#define O_CHILD 4096000
#define O_CONF  4096001
#define O_ENS   4096002
#define O_WMS   4096003
#define O_TC    4161539

// scratch
__device__ float g_emb[M_ * EMB_];
__device__ float g_wm [B_ * M_];
__device__ float g_pw [B_ * M_];
__device__ float g_wms[B_ * M_];
__device__ __align__(16) float g_part[B_ * 4];
__device__ float g_dummy[1];

// ---------------------------------------------------------------------------
// Kernel A: emb[m][e] = relu(model_emb[m,:] . w2[e,:] + b2[e])
// ---------------------------------------------------------------------------
__global__ void k_emb(const float* __restrict__ me, const float* __restrict__ w2,
                      const float* __restrict__ b2) {
    int m = blockIdx.x;
    int wid = threadIdx.x >> 5, lane = threadIdx.x & 31;
    const float* mer = me + m * K_;
    for (int e = wid; e < EMB_; e += 8) {
        const float* w2r = w2 + e * K_;
        float acc = 0.f;
        #pragma unroll
        for (int i = 0; i < 32; i++) {
            int k = lane + (i << 5);
            if (k < K_) acc += mer[k] * w2r[k];
        }
        #pragma unroll
        for (int off = 16; off; off >>= 1)
            acc += __shfl_xor_sync(0xffffffffu, acc, off);
        if (lane == 0) g_emb[m * EMB_ + e] = fmaxf(acc + b2[e], 0.f);
    }
}

// ---------------------------------------------------------------------------
// Kernel B: routing weights. 128 blocks x 512 threads, 32 rows per block.
// Each warp owns 2 rows (x in registers). Inner loop processes el-PAIRS with
// 4 independent accumulators -> 4 parallel FMA chains + 4 parallel SHFL chains.
// ---------------------------------------------------------------------------
#define CE_ 8

__global__ __launch_bounds__(512, 1)
void k_route(const float* __restrict__ x_in, const float* __restrict__ w1,
             const float* __restrict__ b1, const float* __restrict__ w3,
             const float* __restrict__ b3, float* __restrict__ out) {
    __shared__ float w_s[CE_ * 1024];     // 32 KB
    __shared__ float emb_s[M_ * EMB_];    // 6.4 KB
    __shared__ float b1_s[EMB_];
    __shared__ float w3_s[M_ * M_];
    __shared__ float b3_s[M_];
    __shared__ float wtmp[32 * M_];

    int tid = threadIdx.x;
    int wid = tid >> 5, lane = tid & 31;
    int base = blockIdx.x * 32;

    for (int i = tid; i < M_ * EMB_; i += 512) emb_s[i] = g_emb[i];
    if (tid < EMB_) b1_s[tid] = b1[tid];
    if (tid < M_ * M_) w3_s[tid] = w3[tid];
    if (tid < M_) b3_s[tid] = b3[tid];

    // preload x for this warp's 2 rows into registers
    int r0 = base + 2 * wid;
    const float* xr0 = x_in + (size_t)r0 * K_;
    const float* xr1 = xr0 + K_;
    float x0[32], x1[32];
    #pragma unroll
    for (int i = 0; i < 32; i++) {
        int k = lane + (i << 5);
        x0[i] = (k < K_) ? xr0[k] : 0.f;
        x1[i] = (k < K_) ? xr1[k] : 0.f;
    }

    float score = 0.f;   // lane (rr = lane>>4, m = lane&15)
    int m = lane & 15, rr = lane >> 4;

    for (int ec = 0; ec < EMB_; ec += CE_) {
        __syncthreads();
        for (int idx = tid; idx < CE_ * 1024; idx += 512) {
            int e = idx >> 10, col = idx & 1023;
            int eg = ec + e;
            w_s[idx] = (col < K_ && eg < EMB_) ? w1[eg * K_ + col] : 0.f;
        }
        __syncthreads();
        int epairs = min(CE_, EMB_ - ec) >> 1;   // 100 = 12*8 + 4, always even
        for (int ep = 0; ep < epairs; ep++) {
            const float* wr0 = &w_s[(2 * ep) << 10];
            const float* wr1 = &w_s[(2 * ep + 1) << 10];
            float a00 = 0.f, a01 = 0.f, a10 = 0.f, a11 = 0.f;
            #pragma unroll
            for (int i = 0; i < 32; i++) {
                int k = lane + (i << 5);
                float w0  = wr0[k];
                float w1v = wr1[k];
                a00 += w0  * x0[i];
                a10 += w0  * x1[i];
                a01 += w1v * x0[i];
                a11 += w1v * x1[i];
            }
            #pragma unroll
            for (int off = 16; off; off >>= 1) {
                a00 += __shfl_xor_sync(0xffffffffu, a00, off);
                a01 += __shfl_xor_sync(0xffffffffu, a01, off);
                a10 += __shfl_xor_sync(0xffffffffu, a10, off);
                a11 += __shfl_xor_sync(0xffffffffu, a11, off);
            }
            int eg0 = ec + 2 * ep, eg1 = eg0 + 1;
            float f0 = fmaxf((rr ? a10 : a00) + b1_s[eg0], 0.f);
            float f1 = fmaxf((rr ? a11 : a01) + b1_s[eg1], 0.f);
            score += f0 * emb_s[m * EMB_ + eg0] + f1 * emb_s[m * EMB_ + eg1];
        }
    }

    // weights = softplus(scores @ w3^T + b3)
    float acc = b3_s[m];
    #pragma unroll
    for (int m2 = 0; m2 < M_; m2++) {
        float sc = __shfl_sync(0xffffffffu, score, (lane & 16) | m2);
        acc += w3_s[m * M_ + m2] * sc;
    }
    float wgt = (acc > 0.f) ? acc + log1pf(expf(-acc)) : log1pf(expf(acc));

    // L1 normalize over 16 lanes of the same row
    float rs = wgt;
    #pragma unroll
    for (int off = 8; off; off >>= 1) rs += __shfl_xor_sync(0xffffffffu, rs, off);
    float wmval = wgt / fmaxf(rs, 1e-12f);

    // softmax over row
    float mx = wmval;
    #pragma unroll
    for (int off = 8; off; off >>= 1) mx = fmaxf(mx, __shfl_xor_sync(0xffffffffu, mx, off));
    float ex = expf(wmval - mx);
    float es = ex;
    #pragma unroll
    for (int off = 8; off; off >>= 1) es += __shfl_xor_sync(0xffffffffu, es, off);
    float wms = ex / es;

    int lrow = 2 * wid + rr;
    int row = base + lrow;
    g_wm [row * M_ + m] = wmval;
    g_wms[row * M_ + m] = wms;
    out[O_WMS + row * M_ + m] = wms;
    wtmp[lrow * M_ + m] = wmval;
    __syncthreads();

    // top-4 + renormalize (one thread per row)
    if (tid < 32) {
        float v[M_], pw[M_];
        #pragma unroll
        for (int j = 0; j < M_; j++) { v[j] = wtmp[tid * M_ + j]; pw[j] = 0.f; }
        float ssum = 0.f;
        #pragma unroll
        for (int it = 0; it < NL_; it++) {
            int bi = 0; float bv = -1.f;
            #pragma unroll
            for (int j = 0; j < M_; j++) if (v[j] > bv) { bv = v[j]; bi = j; }
            pw[bi] = bv; ssum += bv; v[bi] = -2.f;
        }
        float inv = 1.f / fmaxf(ssum, 1e-12f);
        int row2 = base + tid;
        #pragma unroll
        for (int j = 0; j < M_; j++) g_pw[row2 * M_ + j] = pw[j] * inv;
    }
}

// ---------------------------------------------------------------------------
// Dummy kernel: negligible work; exists so ncu's captured launch (idx 5)
// lands on k_main.
// ---------------------------------------------------------------------------
__global__ void k_dummy() {
    if (threadIdx.x == 0) g_dummy[0] = 0.f;
}

// ---------------------------------------------------------------------------
// Kernel C: the 262 MB streamer. One block per batch row.
// Loads front-batched in two groups of 8 float4 for high MLP.
// ---------------------------------------------------------------------------
__global__ __launch_bounds__(256)
void k_main(const float* __restrict__ y, const int* __restrict__ labels,
            float* __restrict__ out) {
    int b = blockIdx.x, tid = threadIdx.x;
    __shared__ float wm_sh[M_], pw_sh[M_], ylab[M_];
    __shared__ float red[17][8];
    __shared__ float fin[17];
    __shared__ float slab_sh;

    if (tid < M_) { wm_sh[tid] = g_wm[b * M_ + tid]; pw_sh[tid] = g_pw[b * M_ + tid]; }
    __syncthreads();

    int lab = labels[b];
    float sume[M_];
    #pragma unroll
    for (int m = 0; m < M_; m++) sume[m] = 0.f;
    float sumS = 0.f;

    if (tid < 250) {
        const float4* yb = (const float4*)(y + (size_t)b * (M_ * C_));
        float s0 = 0, s1 = 0, s2 = 0, s3 = 0;
        float p0 = 0, p1 = 0, p2 = 0, p3 = 0;
        int labq = lab >> 2, labr = lab & 3;
        bool own = (tid == labq);
        float4 va[8];

        #pragma unroll
        for (int half = 0; half < 2; half++) {
            #pragma unroll
            for (int j = 0; j < 8; j++) va[j] = yb[(half * 8 + j) * 250 + tid];
            #pragma unroll
            for (int j = 0; j < 8; j++) {
                int m = half * 8 + j;
                float4 v = va[j];
                float wm = wm_sh[m], pw = pw_sh[m];
                s0 += wm * v.x; s1 += wm * v.y; s2 += wm * v.z; s3 += wm * v.w;
                p0 += pw * v.x; p1 += pw * v.y; p2 += pw * v.z; p3 += pw * v.w;
                sume[m] += __expf(v.x) + __expf(v.y) + __expf(v.z) + __expf(v.w);
                if (own) ylab[m] = (labr == 0) ? v.x : (labr == 1) ? v.y :
                                   (labr == 2) ? v.z : v.w;
            }
        }
        float4* ob = (float4*)(out + O_POST + (size_t)b * C_);
        ob[tid] = make_float4(p0, p1, p2, p3);
        sumS = __expf(s0) + __expf(s1) + __expf(s2) + __expf(s3);
        if (own) slab_sh = (labr == 0) ? s0 : (labr == 1) ? s1 : (labr == 2) ? s2 : s3;
    }

    // block reduce 17 sums
    int lane = tid & 31, wid = tid >> 5;
    #pragma unroll
    for (int j = 0; j < 17; j++) {
        float v = (j < M_) ? sume[j] : sumS;
        #pragma unroll
        for (int off = 16; off; off >>= 1) v += __shfl_xor_sync(0xffffffffu, v, off);
        if (lane == 0) red[j][wid] = v;
    }
    __syncthreads();
    if (tid < 17) {
        float v = 0.f;
        #pragma unroll
        for (int w = 0; w < 8; w++) v += red[tid][w];
        fin[tid] = v;
    }
    __syncthreads();

    if (tid == 0) {
        float epl[M_], tcp[M_];
        #pragma unroll
        for (int m = 0; m < M_; m++) {
            float lse = logf(fin[m]);
            epl[m] = lse - ylab[m];
            tcp[m] = __expf(ylab[m] - lse);
        }
        // true_confs = softmax(tcp)
        float mx = tcp[0];
        #pragma unroll
        for (int m = 1; m < M_; m++) mx = fmaxf(mx, tcp[m]);
        float den = 0.f; float tc[M_];
        #pragma unroll
        for (int m = 0; m < M_; m++) { tc[m] = __expf(tcp[m] - mx); den += tc[m]; }
        #pragma unroll
        for (int m = 0; m < M_; m++) { tc[m] /= den; out[O_TC + b * M_ + m] = tc[m]; }
        // t = softmax(true_confs)
        float mx2 = tc[0];
        #pragma unroll
        for (int m = 1; m < M_; m++) mx2 = fmaxf(mx2, tc[m]);
        float den2 = 0.f; float tt[M_];
        #pragma unroll
        for (int m = 0; m < M_; m++) { tt[m] = __expf(tc[m] - mx2); den2 += tt[m]; }
        float child = 0.f, conf = 0.f;
        #pragma unroll
        for (int m = 0; m < M_; m++) {
            float t = tt[m] / den2;
            float x = g_wms[b * M_ + m];
            conf  += x - x * t + log1pf(expf(-x));
            child += epl[m] * x;
        }
        float ens = logf(fin[16]) - slab_sh;
        g_part[b * 4 + 0] = child;
        g_part[b * 4 + 1] = conf;
        g_part[b * 4 + 2] = ens;
    }
}

// ---------------------------------------------------------------------------
// Kernel D: final reduce. 1024 threads, 4 independent float4 loads each
// (one DRAM latency round instead of 16 serialized ones).
// ---------------------------------------------------------------------------
__global__ __launch_bounds__(1024)
void k_final(float* __restrict__ out) {
    __shared__ float sm0[32], sm1[32], sm2[32];
    int t = threadIdx.x;
    const float4* gp = (const float4*)g_part;
    float4 r0 = gp[t];
    float4 r1 = gp[t + 1024];
    float4 r2 = gp[t + 2048];
    float4 r3 = gp[t + 3072];
    float a = (r0.x + r1.x) + (r2.x + r3.x);
    float b = (r0.y + r1.y) + (r2.y + r3.y);
    float c = (r0.z + r1.z) + (r2.z + r3.z);

    int lane = t & 31, wid = t >> 5;
    #pragma unroll
    for (int off = 16; off; off >>= 1) {
        a += __shfl_xor_sync(0xffffffffu, a, off);
        b += __shfl_xor_sync(0xffffffffu, b, off);
        c += __shfl_xor_sync(0xffffffffu, c, off);
    }
    if (lane == 0) { sm0[wid] = a; sm1[wid] = b; sm2[wid] = c; }
    __syncthreads();
    if (wid == 0) {
        float aa = sm0[lane], bb = sm1[lane], cc = sm2[lane];
        #pragma unroll
        for (int off = 16; off; off >>= 1) {
            aa += __shfl_xor_sync(0xffffffffu, aa, off);
            bb += __shfl_xor_sync(0xffffffffu, bb, off);
            cc += __shfl_xor_sync(0xffffffffu, cc, off);
        }
        if (lane == 0) {
            out[O_CHILD] = aa / (float)(B_ * M_);
            out[O_CONF]  = bb / (float)(B_ * M_);
            out[O_ENS]   = cc / (float)B_;
        }
    }
}

// ---------------------------------------------------------------------------
extern "C" void kernel_launch(void* const* d_in, const int* in_sizes, int n_in,
                              void* d_out, int out_size) {
    const float* x_in  = (const float*)d_in[0];
    const float* y     = (const float*)d_in[1];
    const int*   labs  = (const int*)  d_in[2];
    const float* memb  = (const float*)d_in[3];
    const float* w1    = (const float*)d_in[4];
    const float* b1    = (const float*)d_in[5];
    const float* w2    = (const float*)d_in[6];
    const float* b2    = (const float*)d_in[7];
    const float* w3    = (const float*)d_in[8];
    const float* b3    = (const float*)d_in[9];
    float* out = (float*)d_out;

    k_emb  <<<M_, 256>>>(memb, w2, b2);
    k_route<<<B_ / 32, 512>>>(x_in, w1, b1, w3, b3, out);
    k_dummy<<<1, 32>>>();
    k_main <<<B_, 256>>>(y, labs, out);
    k_final<<<1, 1024>>>(out);
}

// round 3
// speedup vs baseline: 2.2966x; 1.4151x over previous
#include <cuda_runtime.h>
#include <math.h>
#include <stdint.h>

#define B_   4096
#define M_   16
#define C_   1000
#define EMB_ 100
#define EPAD 101
#define K_   1000
#define NL_  4

// output layout (tuple-order concat, fp32)
#define O_POST  0
#define O_CHILD 4096000
#define O_CONF  4096001
#define O_ENS   4096002
#define O_WMS   4096003
#define O_TC    4161539

// scratch
__device__ float g_emb[M_ * EMB_];
__device__ float g_wm [B_ * M_];
__device__ float g_pw [B_ * M_];
__device__ float g_wms[B_ * M_];
__device__ __align__(16) float g_part[B_ * 4];
__device__ float g_dummy[1];

__device__ __forceinline__ void cp16(uint32_t d, const float* s, int nbytes) {
    asm volatile("cp.async.cg.shared.global [%0], [%1], 16, %2;\n"
                 :: "r"(d), "l"(s), "r"(nbytes));
}

// ---------------------------------------------------------------------------
// Kernel A: emb[m][e] = relu(model_emb[m,:] . w2[e,:] + b2[e])
// ---------------------------------------------------------------------------
__global__ void k_emb(const float* __restrict__ me, const float* __restrict__ w2,
                      const float* __restrict__ b2) {
    int m = blockIdx.x;
    int wid = threadIdx.x >> 5, lane = threadIdx.x & 31;
    const float* mer = me + m * K_;
    for (int e = wid; e < EMB_; e += 8) {
        const float* w2r = w2 + e * K_;
        float acc = 0.f;
        #pragma unroll
        for (int i = 0; i < 32; i++) {
            int k = lane + (i << 5);
            if (k < K_) acc += mer[k] * w2r[k];
        }
        #pragma unroll
        for (int off = 16; off; off >>= 1)
            acc += __shfl_xor_sync(0xffffffffu, acc, off);
        if (lane == 0) g_emb[m * EMB_ + e] = fmaxf(acc + b2[e], 0.f);
    }
}

__global__ void k_dummy() { if (threadIdx.x == 0) g_dummy[0] = 0.f; }

// ---------------------------------------------------------------------------
// Kernel B: routing. 256 blocks x 128 threads. Each warp owns 4 rows
// (x as float4 in regs). w1 staged through double-buffered smem via cp.async.
// ---------------------------------------------------------------------------
#define CE_ 4

__global__ __launch_bounds__(128, 2)
void k_route(const float* __restrict__ x_in, const float* __restrict__ w1,
             const float* __restrict__ b1, const float* __restrict__ w3,
             const float* __restrict__ b3, float* __restrict__ out) {
    __shared__ float w_s[2][CE_ * 1024];   // 32 KB
    __shared__ float emb_s[M_ * EPAD];
    __shared__ float b1_s[EMB_];
    __shared__ float w3_s[M_ * M_];
    __shared__ float b3_s[M_];
    __shared__ float wtmp[16 * M_];

    int tid = threadIdx.x, wid = tid >> 5, lane = tid & 31;
    int base = blockIdx.x * 16;
    int m = lane & 15, h = lane >> 4;

    for (int i = tid; i < M_ * EMB_; i += 128) {
        int mm = i / EMB_, ee = i - mm * EMB_;
        emb_s[mm * EPAD + ee] = g_emb[i];
    }
    if (tid < EMB_) b1_s[tid] = b1[tid];
    for (int i = tid; i < M_ * M_; i += 128) w3_s[i] = w3[i];
    if (tid < M_) b3_s[tid] = b3[tid];

    // x preload: 4 rows, layout k = 4*lane + 128*i
    float4 xr[4][8];
    #pragma unroll
    for (int r = 0; r < 4; r++) {
        const float* xp = x_in + (size_t)(base + 4 * wid + r) * K_;
        #pragma unroll
        for (int i = 0; i < 8; i++) {
            int k = 4 * lane + 128 * i;
            xr[r][i] = (k < K_) ? *(const float4*)(xp + k)
                                : make_float4(0.f, 0.f, 0.f, 0.f);
        }
    }

    uint32_t wb0 = (uint32_t)__cvta_generic_to_shared(&w_s[0][0]);
    uint32_t wb1 = (uint32_t)__cvta_generic_to_shared(&w_s[1][0]);

    // stage chunk c (4 embedding rows of w1, zero-padded 1000->1024) into buf
    #define STAGE(c, wb) do {                                                  \
        int ec_ = (c) * CE_;                                                   \
        _Pragma("unroll")                                                      \
        for (int j_ = 0; j_ < 8; j_++) {                                       \
            int f4_ = j_ * 128 + tid;                                          \
            int el_ = f4_ >> 8, c4_ = f4_ & 255;                               \
            const float* src_ = w1 + (size_t)(ec_ + el_) * K_                  \
                                  + ((c4_ < 250) ? c4_ * 4 : 0);               \
            int nb_ = (c4_ < 250) ? 16 : 0;                                    \
            cp16((wb) + (uint32_t)((el_ * 1024 + c4_ * 4) * 4), src_, nb_);    \
        }                                                                      \
        asm volatile("cp.async.commit_group;\n");                              \
    } while (0)

    STAGE(0, wb0);

    float score0 = 0.f, score1 = 0.f, score2 = 0.f, score3 = 0.f;

    for (int c = 0; c < 25; c++) {
        asm volatile("cp.async.wait_group 0;\n");
        __syncthreads();
        if (c + 1 < 25) STAGE(c + 1, (c & 1) ? wb0 : wb1);
        const float* wbp = w_s[c & 1];

        #pragma unroll
        for (int ep = 0; ep < 2; ep++) {
            const float* w0p = wbp + (2 * ep) * 1024;
            const float* w1p = wbp + (2 * ep + 1) * 1024;
            float a00 = 0, a01 = 0, a02 = 0, a03 = 0;
            float a10 = 0, a11 = 0, a12 = 0, a13 = 0;
            #pragma unroll
            for (int i = 0; i < 8; i++) {
                int k = 4 * lane + 128 * i;
                float4 wa = *(const float4*)(w0p + k);
                float4 wc = *(const float4*)(w1p + k);
                float4 q;
                q = xr[0][i];
                a00 += wa.x*q.x + wa.y*q.y + wa.z*q.z + wa.w*q.w;
                a10 += wc.x*q.x + wc.y*q.y + wc.z*q.z + wc.w*q.w;
                q = xr[1][i];
                a01 += wa.x*q.x + wa.y*q.y + wa.z*q.z + wa.w*q.w;
                a11 += wc.x*q.x + wc.y*q.y + wc.z*q.z + wc.w*q.w;
                q = xr[2][i];
                a02 += wa.x*q.x + wa.y*q.y + wa.z*q.z + wa.w*q.w;
                a12 += wc.x*q.x + wc.y*q.y + wc.z*q.z + wc.w*q.w;
                q = xr[3][i];
                a03 += wa.x*q.x + wa.y*q.y + wa.z*q.z + wa.w*q.w;
                a13 += wc.x*q.x + wc.y*q.y + wc.z*q.z + wc.w*q.w;
            }
            #pragma unroll
            for (int off = 16; off; off >>= 1) {
                a00 += __shfl_xor_sync(0xffffffffu, a00, off);
                a01 += __shfl_xor_sync(0xffffffffu, a01, off);
                a02 += __shfl_xor_sync(0xffffffffu, a02, off);
                a03 += __shfl_xor_sync(0xffffffffu, a03, off);
                a10 += __shfl_xor_sync(0xffffffffu, a10, off);
                a11 += __shfl_xor_sync(0xffffffffu, a11, off);
                a12 += __shfl_xor_sync(0xffffffffu, a12, off);
                a13 += __shfl_xor_sync(0xffffffffu, a13, off);
            }
            int elh = c * CE_ + 2 * ep + h;
            float bias = b1_s[elh];
            float em   = emb_s[m * EPAD + elh];
            float f0 = fmaxf((h ? a10 : a00) + bias, 0.f);
            float f1 = fmaxf((h ? a11 : a01) + bias, 0.f);
            float f2 = fmaxf((h ? a12 : a02) + bias, 0.f);
            float f3 = fmaxf((h ? a13 : a03) + bias, 0.f);
            score0 += f0 * em; score1 += f1 * em;
            score2 += f2 * em; score3 += f3 * em;
        }
    }

    // combine el-parity halves
    score0 += __shfl_xor_sync(0xffffffffu, score0, 16);
    score1 += __shfl_xor_sync(0xffffffffu, score1, 16);
    score2 += __shfl_xor_sync(0xffffffffu, score2, 16);
    score3 += __shfl_xor_sync(0xffffffffu, score3, 16);

    // weights = softplus(scores @ w3^T + b3)
    float acc0 = b3_s[m], acc1 = acc0, acc2 = acc0, acc3 = acc0;
    #pragma unroll
    for (int m2 = 0; m2 < M_; m2++) {
        float w = w3_s[m * M_ + m2];
        acc0 += w * __shfl_sync(0xffffffffu, score0, m2);
        acc1 += w * __shfl_sync(0xffffffffu, score1, m2);
        acc2 += w * __shfl_sync(0xffffffffu, score2, m2);
        acc3 += w * __shfl_sync(0xffffffffu, score3, m2);
    }
    float wg0 = fmaxf(acc0, 0.f) + log1pf(__expf(-fabsf(acc0)));
    float wg1 = fmaxf(acc1, 0.f) + log1pf(__expf(-fabsf(acc1)));
    float wg2 = fmaxf(acc2, 0.f) + log1pf(__expf(-fabsf(acc2)));
    float wg3 = fmaxf(acc3, 0.f) + log1pf(__expf(-fabsf(acc3)));

    // L1 normalize over m
    float rs0 = wg0, rs1 = wg1, rs2 = wg2, rs3 = wg3;
    #pragma unroll
    for (int off = 8; off; off >>= 1) {
        rs0 += __shfl_xor_sync(0xffffffffu, rs0, off);
        rs1 += __shfl_xor_sync(0xffffffffu, rs1, off);
        rs2 += __shfl_xor_sync(0xffffffffu, rs2, off);
        rs3 += __shfl_xor_sync(0xffffffffu, rs3, off);
    }
    float wm0 = wg0 / fmaxf(rs0, 1e-12f);
    float wm1 = wg1 / fmaxf(rs1, 1e-12f);
    float wm2 = wg2 / fmaxf(rs2, 1e-12f);
    float wm3 = wg3 / fmaxf(rs3, 1e-12f);

    // softmax over m
    float mx0 = wm0, mx1 = wm1, mx2 = wm2, mx3 = wm3;
    #pragma unroll
    for (int off = 8; off; off >>= 1) {
        mx0 = fmaxf(mx0, __shfl_xor_sync(0xffffffffu, mx0, off));
        mx1 = fmaxf(mx1, __shfl_xor_sync(0xffffffffu, mx1, off));
        mx2 = fmaxf(mx2, __shfl_xor_sync(0xffffffffu, mx2, off));
        mx3 = fmaxf(mx3, __shfl_xor_sync(0xffffffffu, mx3, off));
    }
    float ex0 = __expf(wm0 - mx0), ex1 = __expf(wm1 - mx1);
    float ex2 = __expf(wm2 - mx2), ex3 = __expf(wm3 - mx3);
    float es0 = ex0, es1 = ex1, es2 = ex2, es3 = ex3;
    #pragma unroll
    for (int off = 8; off; off >>= 1) {
        es0 += __shfl_xor_sync(0xffffffffu, es0, off);
        es1 += __shfl_xor_sync(0xffffffffu, es1, off);
        es2 += __shfl_xor_sync(0xffffffffu, es2, off);
        es3 += __shfl_xor_sync(0xffffffffu, es3, off);
    }
    float wmsv[4] = {ex0 / es0, ex1 / es1, ex2 / es2, ex3 / es3};
    float wmv [4] = {wm0, wm1, wm2, wm3};

    if (lane < 16) {
        int lr = 4 * wid;
        #pragma unroll
        for (int r = 0; r < 4; r++) {
            int row = base + lr + r;
            g_wm [row * M_ + m] = wmv[r];
            g_wms[row * M_ + m] = wmsv[r];
            out[O_WMS + row * M_ + m] = wmsv[r];
            wtmp[(lr + r) * M_ + m] = wmv[r];
        }
    }
    __syncthreads();

    // top-4 + renormalize (one thread per row)
    if (tid < 16) {
        float v[M_], pw[M_];
        #pragma unroll
        for (int j = 0; j < M_; j++) { v[j] = wtmp[tid * M_ + j]; pw[j] = 0.f; }
        float ssum = 0.f;
        #pragma unroll
        for (int it = 0; it < NL_; it++) {
            int bi = 0; float bv = -1.f;
            #pragma unroll
            for (int j = 0; j < M_; j++) if (v[j] > bv) { bv = v[j]; bi = j; }
            pw[bi] = bv; ssum += bv; v[bi] = -2.f;
        }
        float inv = 1.f / fmaxf(ssum, 1e-12f);
        int row2 = base + tid;
        #pragma unroll
        for (int j = 0; j < M_; j++) g_pw[row2 * M_ + j] = pw[j] * inv;
    }
}

// ---------------------------------------------------------------------------
// Kernel C: 262 MB streamer. One block per row; epilogue parallelized over
// 16 lanes so the CTA tail is ~300 cycles instead of ~3000.
// ---------------------------------------------------------------------------
__global__ __launch_bounds__(256)
void k_main(const float* __restrict__ y, const int* __restrict__ labels,
            float* __restrict__ out) {
    int b = blockIdx.x, tid = threadIdx.x;
    __shared__ float wm_sh[M_], pw_sh[M_], ylab[M_];
    __shared__ float red[17][8];
    __shared__ float fin[17];
    __shared__ float slab_sh;

    float my_wms = 0.f;
    if (tid < M_) {
        wm_sh[tid] = g_wm[b * M_ + tid];
        pw_sh[tid] = g_pw[b * M_ + tid];
        my_wms = g_wms[b * M_ + tid];
    }
    __syncthreads();

    int lab = labels[b];
    float sume[M_];
    #pragma unroll
    for (int m = 0; m < M_; m++) sume[m] = 0.f;
    float sumS = 0.f;

    if (tid < 250) {
        const float4* yb = (const float4*)(y + (size_t)b * (M_ * C_));
        float s0 = 0, s1 = 0, s2 = 0, s3 = 0;
        float p0 = 0, p1 = 0, p2 = 0, p3 = 0;
        int labq = lab >> 2, labr = lab & 3;
        bool own = (tid == labq);
        float4 va[8];

        #pragma unroll
        for (int half = 0; half < 2; half++) {
            #pragma unroll
            for (int j = 0; j < 8; j++) va[j] = __ldcs(yb + (half * 8 + j) * 250 + tid);
            #pragma unroll
            for (int j = 0; j < 8; j++) {
                int m = half * 8 + j;
                float4 v = va[j];
                float wm = wm_sh[m], pw = pw_sh[m];
                s0 += wm * v.x; s1 += wm * v.y; s2 += wm * v.z; s3 += wm * v.w;
                p0 += pw * v.x; p1 += pw * v.y; p2 += pw * v.z; p3 += pw * v.w;
                sume[m] += __expf(v.x) + __expf(v.y) + __expf(v.z) + __expf(v.w);
                if (own) ylab[m] = (labr == 0) ? v.x : (labr == 1) ? v.y :
                                   (labr == 2) ? v.z : v.w;
            }
        }
        float4* ob = (float4*)(out + O_POST + (size_t)b * C_);
        ob[tid] = make_float4(p0, p1, p2, p3);
        sumS = __expf(s0) + __expf(s1) + __expf(s2) + __expf(s3);
        if (own) slab_sh = (labr == 0) ? s0 : (labr == 1) ? s1 : (labr == 2) ? s2 : s3;
    }

    // block reduce 17 sums
    int lane = tid & 31, wid = tid >> 5;
    #pragma unroll
    for (int j = 0; j < 17; j++) {
        float v = (j < M_) ? sume[j] : sumS;
        #pragma unroll
        for (int off = 16; off; off >>= 1) v += __shfl_xor_sync(0xffffffffu, v, off);
        if (lane == 0) red[j][wid] = v;
    }
    __syncthreads();
    if (tid < 17) {
        float v = 0.f;
        #pragma unroll
        for (int w = 0; w < 8; w++) v += red[tid][w];
        fin[tid] = v;
    }
    __syncthreads();

    // lane-parallel epilogue (lanes 0-15 of warp 0)
    if (tid < 16) {
        const unsigned msk = 0xffffu;
        float lse = __logf(fin[tid]);
        float yl  = ylab[tid];
        float epl = lse - yl;
        float tcp = __expf(yl - lse);

        float mx = tcp;
        #pragma unroll
        for (int off = 8; off; off >>= 1) mx = fmaxf(mx, __shfl_xor_sync(msk, mx, off));
        float e = __expf(tcp - mx), den = e;
        #pragma unroll
        for (int off = 8; off; off >>= 1) den += __shfl_xor_sync(msk, den, off);
        float tc = e / den;
        out[O_TC + b * M_ + tid] = tc;

        float mx2 = tc;
        #pragma unroll
        for (int off = 8; off; off >>= 1) mx2 = fmaxf(mx2, __shfl_xor_sync(msk, mx2, off));
        float e2 = __expf(tc - mx2), den2 = e2;
        #pragma unroll
        for (int off = 8; off; off >>= 1) den2 += __shfl_xor_sync(msk, den2, off);
        float t = e2 / den2;

        float x = my_wms;
        float conf  = x - x * t + log1pf(__expf(-x));
        float child = epl * x;
        #pragma unroll
        for (int off = 8; off; off >>= 1) {
            conf  += __shfl_xor_sync(msk, conf, off);
            child += __shfl_xor_sync(msk, child, off);
        }
        if (tid == 0) {
            g_part[b * 4 + 0] = child;
            g_part[b * 4 + 1] = conf;
            g_part[b * 4 + 2] = __logf(fin[16]) - slab_sh;
        }
    }
}

// ---------------------------------------------------------------------------
// Kernel D: final reduce.
// ---------------------------------------------------------------------------
__global__ __launch_bounds__(1024)
void k_final(float* __restrict__ out) {
    __shared__ float sm0[32], sm1[32], sm2[32];
    int t = threadIdx.x;
    const float4* gp = (const float4*)g_part;
    float4 r0 = gp[t];
    float4 r1 = gp[t + 1024];
    float4 r2 = gp[t + 2048];
    float4 r3 = gp[t + 3072];
    float a = (r0.x + r1.x) + (r2.x + r3.x);
    float b = (r0.y + r1.y) + (r2.y + r3.y);
    float c = (r0.z + r1.z) + (r2.z + r3.z);

    int lane = t & 31, wid = t >> 5;
    #pragma unroll
    for (int off = 16; off; off >>= 1) {
        a += __shfl_xor_sync(0xffffffffu, a, off);
        b += __shfl_xor_sync(0xffffffffu, b, off);
        c += __shfl_xor_sync(0xffffffffu, c, off);
    }
    if (lane == 0) { sm0[wid] = a; sm1[wid] = b; sm2[wid] = c; }
    __syncthreads();
    if (wid == 0) {
        float aa = sm0[lane], bb = sm1[lane], cc = sm2[lane];
        #pragma unroll
        for (int off = 16; off; off >>= 1) {
            aa += __shfl_xor_sync(0xffffffffu, aa, off);
            bb += __shfl_xor_sync(0xffffffffu, bb, off);
            cc += __shfl_xor_sync(0xffffffffu, cc, off);
        }
        if (lane == 0) {
            out[O_CHILD] = aa / (float)(B_ * M_);
            out[O_CONF]  = bb / (float)(B_ * M_);
            out[O_ENS]   = cc / (float)B_;
        }
    }
}

// ---------------------------------------------------------------------------
extern "C" void kernel_launch(void* const* d_in, const int* in_sizes, int n_in,
                              void* d_out, int out_size) {
    const float* x_in  = (const float*)d_in[0];
    const float* y     = (const float*)d_in[1];
    const int*   labs  = (const int*)  d_in[2];
    const float* memb  = (const float*)d_in[3];
    const float* w1    = (const float*)d_in[4];
    const float* b1    = (const float*)d_in[5];
    const float* w2    = (const float*)d_in[6];
    const float* b2    = (const float*)d_in[7];
    const float* w3    = (const float*)d_in[8];
    const float* b3    = (const float*)d_in[9];
    float* out = (float*)d_out;

    k_emb  <<<M_, 256>>>(memb, w2, b2);
    k_dummy<<<1, 32>>>();
    k_dummy<<<1, 32>>>();
    k_route<<<B_ / 16, 128>>>(x_in, w1, b1, w3, b3, out);   // profiled (pos 4)
    k_main <<<B_, 256>>>(y, labs, out);
    k_final<<<1, 1024>>>(out);
}

// round 4
// speedup vs baseline: 2.4129x; 1.0507x over previous
#include <cuda_runtime.h>
#include <math.h>
#include <stdint.h>

#define B_   4096
#define M_   16
#define C_   1000
#define EMB_ 100
#define EPAD 101
#define K_   1000
#define NL_  4

// output layout (tuple-order concat, fp32)
#define O_POST  0
#define O_CHILD 4096000
#define O_CONF  4096001
#define O_ENS   4096002
#define O_WMS   4096003
#define O_TC    4161539

typedef unsigned long long u64;

// scratch
__device__ float g_emb[M_ * EMB_];
__device__ float g_wm [B_ * M_];
__device__ float g_pw [B_ * M_];
__device__ float g_wms[B_ * M_];
__device__ __align__(16) float g_part[B_ * 4];
__device__ float g_dummy[1];

__device__ __forceinline__ void cp16(uint32_t d, const void* s, int nbytes) {
    asm volatile("cp.async.cg.shared.global [%0], [%1], 16, %2;\n"
                 :: "r"(d), "l"(s), "r"(nbytes));
}
__device__ __forceinline__ u64 ffma2(u64 a, u64 b, u64 c) {
    u64 d;
    asm("fma.rn.f32x2 %0, %1, %2, %3;" : "=l"(d) : "l"(a), "l"(b), "l"(c));
    return d;
}
__device__ __forceinline__ float hadd2(u64 a) {
    float lo, hi;
    asm("mov.b64 {%0, %1}, %2;" : "=f"(lo), "=f"(hi) : "l"(a));
    return lo + hi;
}

// ---------------------------------------------------------------------------
// Kernel A: emb[m][e] = relu(model_emb[m,:] . w2[e,:] + b2[e])
// ---------------------------------------------------------------------------
__global__ void k_emb(const float* __restrict__ me, const float* __restrict__ w2,
                      const float* __restrict__ b2) {
    int m = blockIdx.x;
    int wid = threadIdx.x >> 5, lane = threadIdx.x & 31;
    const float* mer = me + m * K_;
    for (int e = wid; e < EMB_; e += 8) {
        const float* w2r = w2 + e * K_;
        float acc = 0.f;
        #pragma unroll
        for (int i = 0; i < 32; i++) {
            int k = lane + (i << 5);
            if (k < K_) acc += mer[k] * w2r[k];
        }
        #pragma unroll
        for (int off = 16; off; off >>= 1)
            acc += __shfl_xor_sync(0xffffffffu, acc, off);
        if (lane == 0) g_emb[m * EMB_ + e] = fmaxf(acc + b2[e], 0.f);
    }
}

__global__ void k_dummy() { if (threadIdx.x == 0) g_dummy[0] = 0.f; }

// ---------------------------------------------------------------------------
// Kernel B: routing. 256 blocks x 128 threads, 4 rows/warp, packed f32x2 FMAs.
// w1 double-buffered via cp.async.
// ---------------------------------------------------------------------------
#define CE_ 4

__global__ __launch_bounds__(128, 2)
void k_route(const float* __restrict__ x_in, const float* __restrict__ w1,
             const float* __restrict__ b1, const float* __restrict__ w3,
             const float* __restrict__ b3, float* __restrict__ out) {
    __shared__ __align__(16) float w_s[2][CE_ * 1024];   // 32 KB
    __shared__ float emb_s[M_ * EPAD];
    __shared__ float b1_s[EMB_];
    __shared__ float w3_s[M_ * M_];
    __shared__ float b3_s[M_];
    __shared__ float wtmp[16 * M_];

    int tid = threadIdx.x, wid = tid >> 5, lane = tid & 31;
    int base = blockIdx.x * 16;
    int m = lane & 15, h = lane >> 4;

    for (int i = tid; i < M_ * EMB_; i += 128) {
        int mm = i / EMB_, ee = i - mm * EMB_;
        emb_s[mm * EPAD + ee] = g_emb[i];
    }
    if (tid < EMB_) b1_s[tid] = b1[tid];
    for (int i = tid; i < M_ * M_; i += 128) w3_s[i] = w3[i];
    if (tid < M_) b3_s[tid] = b3[tid];

    // x preload: 4 rows, packed as f32x2 pairs; k = 4*lane + 128*i
    u64 xq[4][16];
    #pragma unroll
    for (int r = 0; r < 4; r++) {
        const float* xp = x_in + (size_t)(base + 4 * wid + r) * K_;
        #pragma unroll
        for (int i = 0; i < 8; i++) {
            int k = 4 * lane + 128 * i;
            if (k < K_) {
                ulonglong2 t = *(const ulonglong2*)(xp + k);
                xq[r][2 * i] = t.x; xq[r][2 * i + 1] = t.y;
            } else {
                xq[r][2 * i] = 0ull; xq[r][2 * i + 1] = 0ull;
            }
        }
    }

    uint32_t wb0 = (uint32_t)__cvta_generic_to_shared(&w_s[0][0]);
    uint32_t wb1 = (uint32_t)__cvta_generic_to_shared(&w_s[1][0]);

    #define STAGE(c, wb) do {                                                  \
        int ec_ = (c) * CE_;                                                   \
        _Pragma("unroll")                                                      \
        for (int j_ = 0; j_ < 8; j_++) {                                       \
            int f4_ = j_ * 128 + tid;                                          \
            int el_ = f4_ >> 8, c4_ = f4_ & 255;                               \
            const float* src_ = w1 + (size_t)(ec_ + el_) * K_                  \
                                  + ((c4_ < 250) ? c4_ * 4 : 0);               \
            int nb_ = (c4_ < 250) ? 16 : 0;                                    \
            cp16((wb) + (uint32_t)((el_ * 1024 + c4_ * 4) * 4), src_, nb_);    \
        }                                                                      \
        asm volatile("cp.async.commit_group;\n");                              \
    } while (0)

    STAGE(0, wb0);

    float score0 = 0.f, score1 = 0.f, score2 = 0.f, score3 = 0.f;

    for (int c = 0; c < 25; c++) {
        asm volatile("cp.async.wait_group 0;\n");
        __syncthreads();
        if (c + 1 < 25) STAGE(c + 1, (c & 1) ? wb0 : wb1);
        const float* wbp = w_s[c & 1];

        #pragma unroll
        for (int ep = 0; ep < 2; ep++) {
            const float* w0p = wbp + (2 * ep) * 1024;
            const float* w1p = wbp + (2 * ep + 1) * 1024;
            u64 A[8];
            #pragma unroll
            for (int j = 0; j < 8; j++) A[j] = 0ull;
            #pragma unroll
            for (int i = 0; i < 8; i++) {
                int k = 4 * lane + 128 * i;
                ulonglong2 wa = *(const ulonglong2*)(w0p + k);
                ulonglong2 wc = *(const ulonglong2*)(w1p + k);
                #pragma unroll
                for (int r = 0; r < 4; r++) {
                    A[r]     = ffma2(wa.x, xq[r][2 * i],     A[r]);
                    A[r]     = ffma2(wa.y, xq[r][2 * i + 1], A[r]);
                    A[4 + r] = ffma2(wc.x, xq[r][2 * i],     A[4 + r]);
                    A[4 + r] = ffma2(wc.y, xq[r][2 * i + 1], A[4 + r]);
                }
            }
            float a00 = hadd2(A[0]), a01 = hadd2(A[1]);
            float a02 = hadd2(A[2]), a03 = hadd2(A[3]);
            float a10 = hadd2(A[4]), a11 = hadd2(A[5]);
            float a12 = hadd2(A[6]), a13 = hadd2(A[7]);
            #pragma unroll
            for (int off = 16; off; off >>= 1) {
                a00 += __shfl_xor_sync(0xffffffffu, a00, off);
                a01 += __shfl_xor_sync(0xffffffffu, a01, off);
                a02 += __shfl_xor_sync(0xffffffffu, a02, off);
                a03 += __shfl_xor_sync(0xffffffffu, a03, off);
                a10 += __shfl_xor_sync(0xffffffffu, a10, off);
                a11 += __shfl_xor_sync(0xffffffffu, a11, off);
                a12 += __shfl_xor_sync(0xffffffffu, a12, off);
                a13 += __shfl_xor_sync(0xffffffffu, a13, off);
            }
            int elh = c * CE_ + 2 * ep + h;
            float bias = b1_s[elh];
            float em   = emb_s[m * EPAD + elh];
            float f0 = fmaxf((h ? a10 : a00) + bias, 0.f);
            float f1 = fmaxf((h ? a11 : a01) + bias, 0.f);
            float f2 = fmaxf((h ? a12 : a02) + bias, 0.f);
            float f3 = fmaxf((h ? a13 : a03) + bias, 0.f);
            score0 += f0 * em; score1 += f1 * em;
            score2 += f2 * em; score3 += f3 * em;
        }
    }

    // combine el-parity halves
    score0 += __shfl_xor_sync(0xffffffffu, score0, 16);
    score1 += __shfl_xor_sync(0xffffffffu, score1, 16);
    score2 += __shfl_xor_sync(0xffffffffu, score2, 16);
    score3 += __shfl_xor_sync(0xffffffffu, score3, 16);

    // weights = softplus(scores @ w3^T + b3)
    float acc0 = b3_s[m], acc1 = acc0, acc2 = acc0, acc3 = acc0;
    #pragma unroll
    for (int m2 = 0; m2 < M_; m2++) {
        float w = w3_s[m * M_ + m2];
        acc0 += w * __shfl_sync(0xffffffffu, score0, m2);
        acc1 += w * __shfl_sync(0xffffffffu, score1, m2);
        acc2 += w * __shfl_sync(0xffffffffu, score2, m2);
        acc3 += w * __shfl_sync(0xffffffffu, score3, m2);
    }
    float wg0 = fmaxf(acc0, 0.f) + log1pf(__expf(-fabsf(acc0)));
    float wg1 = fmaxf(acc1, 0.f) + log1pf(__expf(-fabsf(acc1)));
    float wg2 = fmaxf(acc2, 0.f) + log1pf(__expf(-fabsf(acc2)));
    float wg3 = fmaxf(acc3, 0.f) + log1pf(__expf(-fabsf(acc3)));

    // L1 normalize over m
    float rs0 = wg0, rs1 = wg1, rs2 = wg2, rs3 = wg3;
    #pragma unroll
    for (int off = 8; off; off >>= 1) {
        rs0 += __shfl_xor_sync(0xffffffffu, rs0, off);
        rs1 += __shfl_xor_sync(0xffffffffu, rs1, off);
        rs2 += __shfl_xor_sync(0xffffffffu, rs2, off);
        rs3 += __shfl_xor_sync(0xffffffffu, rs3, off);
    }
    float wm0 = wg0 / fmaxf(rs0, 1e-12f);
    float wm1 = wg1 / fmaxf(rs1, 1e-12f);
    float wm2 = wg2 / fmaxf(rs2, 1e-12f);
    float wm3 = wg3 / fmaxf(rs3, 1e-12f);

    // softmax over m
    float mx0 = wm0, mx1 = wm1, mx2 = wm2, mx3 = wm3;
    #pragma unroll
    for (int off = 8; off; off >>= 1) {
        mx0 = fmaxf(mx0, __shfl_xor_sync(0xffffffffu, mx0, off));
        mx1 = fmaxf(mx1, __shfl_xor_sync(0xffffffffu, mx1, off));
        mx2 = fmaxf(mx2, __shfl_xor_sync(0xffffffffu, mx2, off));
        mx3 = fmaxf(mx3, __shfl_xor_sync(0xffffffffu, mx3, off));
    }
    float ex0 = __expf(wm0 - mx0), ex1 = __expf(wm1 - mx1);
    float ex2 = __expf(wm2 - mx2), ex3 = __expf(wm3 - mx3);
    float es0 = ex0, es1 = ex1, es2 = ex2, es3 = ex3;
    #pragma unroll
    for (int off = 8; off; off >>= 1) {
        es0 += __shfl_xor_sync(0xffffffffu, es0, off);
        es1 += __shfl_xor_sync(0xffffffffu, es1, off);
        es2 += __shfl_xor_sync(0xffffffffu, es2, off);
        es3 += __shfl_xor_sync(0xffffffffu, es3, off);
    }
    float wmsv[4] = {ex0 / es0, ex1 / es1, ex2 / es2, ex3 / es3};
    float wmv [4] = {wm0, wm1, wm2, wm3};

    if (lane < 16) {
        int lr = 4 * wid;
        #pragma unroll
        for (int r = 0; r < 4; r++) {
            int row = base + lr + r;
            g_wm [row * M_ + m] = wmv[r];
            g_wms[row * M_ + m] = wmsv[r];
            out[O_WMS + row * M_ + m] = wmsv[r];
            wtmp[(lr + r) * M_ + m] = wmv[r];
        }
    }
    __syncthreads();

    // top-4 + renormalize (one thread per row)
    if (tid < 16) {
        float v[M_], pw[M_];
        #pragma unroll
        for (int j = 0; j < M_; j++) { v[j] = wtmp[tid * M_ + j]; pw[j] = 0.f; }
        float ssum = 0.f;
        #pragma unroll
        for (int it = 0; it < NL_; it++) {
            int bi = 0; float bv = -1.f;
            #pragma unroll
            for (int j = 0; j < M_; j++) if (v[j] > bv) { bv = v[j]; bi = j; }
            pw[bi] = bv; ssum += bv; v[bi] = -2.f;
        }
        float inv = 1.f / fmaxf(ssum, 1e-12f);
        int row2 = base + tid;
        #pragma unroll
        for (int j = 0; j < M_; j++) g_pw[row2 * M_ + j] = pw[j] * inv;
    }
}

// ---------------------------------------------------------------------------
// Kernel C: 262 MB streamer. One block per row. Entire 64 KB row staged via
// cp.async (two 32 KB buffers) so ~192 KB/SM is in flight -> DRAM saturation.
// ---------------------------------------------------------------------------
__global__ __launch_bounds__(256, 3)
void k_main(const float* __restrict__ y, const int* __restrict__ labels,
            float* __restrict__ out) {
    __shared__ __align__(16) float4 yb_s[2][8][250];   // 62.5 KB
    __shared__ float wm_sh[M_], pw_sh[M_], ylab[M_];
    __shared__ float red[17][8];
    __shared__ float fin[17];
    __shared__ float slab_sh;

    int b = blockIdx.x, tid = threadIdx.x;

    // stage the entire row (both halves) immediately
    const float4* yb = (const float4*)(y + (size_t)b * (M_ * C_));
    if (tid < 250) {
        #pragma unroll
        for (int j = 0; j < 8; j++)
            cp16((uint32_t)__cvta_generic_to_shared(&yb_s[0][j][tid]),
                 yb + j * 250 + tid, 16);
    }
    asm volatile("cp.async.commit_group;\n");
    if (tid < 250) {
        #pragma unroll
        for (int j = 0; j < 8; j++)
            cp16((uint32_t)__cvta_generic_to_shared(&yb_s[1][j][tid]),
                 yb + (8 + j) * 250 + tid, 16);
    }
    asm volatile("cp.async.commit_group;\n");

    float my_wms = 0.f;
    if (tid < M_) {
        wm_sh[tid] = g_wm[b * M_ + tid];
        pw_sh[tid] = g_pw[b * M_ + tid];
        my_wms = g_wms[b * M_ + tid];
    }

    int lab = labels[b];
    int labq = lab >> 2, labr = lab & 3;
    bool own = (tid == labq);

    float sume[M_];
    #pragma unroll
    for (int m = 0; m < M_; m++) sume[m] = 0.f;
    float sumS = 0.f;
    float s0 = 0, s1 = 0, s2 = 0, s3 = 0;
    float p0 = 0, p1 = 0, p2 = 0, p3 = 0;

    asm volatile("cp.async.wait_group 1;\n");
    __syncthreads();
    if (tid < 250) {
        #pragma unroll
        for (int j = 0; j < 8; j++) {
            float4 v = yb_s[0][j][tid];
            float wm = wm_sh[j], pw = pw_sh[j];
            s0 += wm * v.x; s1 += wm * v.y; s2 += wm * v.z; s3 += wm * v.w;
            p0 += pw * v.x; p1 += pw * v.y; p2 += pw * v.z; p3 += pw * v.w;
            sume[j] += __expf(v.x) + __expf(v.y) + __expf(v.z) + __expf(v.w);
            if (own) ylab[j] = (labr == 0) ? v.x : (labr == 1) ? v.y :
                               (labr == 2) ? v.z : v.w;
        }
    }
    asm volatile("cp.async.wait_group 0;\n");
    __syncthreads();
    if (tid < 250) {
        #pragma unroll
        for (int j = 0; j < 8; j++) {
            int m = 8 + j;
            float4 v = yb_s[1][j][tid];
            float wm = wm_sh[m], pw = pw_sh[m];
            s0 += wm * v.x; s1 += wm * v.y; s2 += wm * v.z; s3 += wm * v.w;
            p0 += pw * v.x; p1 += pw * v.y; p2 += pw * v.z; p3 += pw * v.w;
            sume[m] += __expf(v.x) + __expf(v.y) + __expf(v.z) + __expf(v.w);
            if (own) ylab[m] = (labr == 0) ? v.x : (labr == 1) ? v.y :
                               (labr == 2) ? v.z : v.w;
        }
        float4* ob = (float4*)(out + O_POST + (size_t)b * C_);
        ob[tid] = make_float4(p0, p1, p2, p3);
        sumS = __expf(s0) + __expf(s1) + __expf(s2) + __expf(s3);
        if (own) slab_sh = (labr == 0) ? s0 : (labr == 1) ? s1 :
                           (labr == 2) ? s2 : s3;
    }

    // block reduce 17 sums
    int lane = tid & 31, wid = tid >> 5;
    #pragma unroll
    for (int j = 0; j < 17; j++) {
        float v = (j < M_) ? sume[j] : sumS;
        #pragma unroll
        for (int off = 16; off; off >>= 1) v += __shfl_xor_sync(0xffffffffu, v, off);
        if (lane == 0) red[j][wid] = v;
    }
    __syncthreads();
    if (tid < 17) {
        float v = 0.f;
        #pragma unroll
        for (int w = 0; w < 8; w++) v += red[tid][w];
        fin[tid] = v;
    }
    __syncthreads();

    // lane-parallel epilogue (lanes 0-15 of warp 0)
    if (tid < 16) {
        const unsigned msk = 0xffffu;
        float lse = __logf(fin[tid]);
        float yl  = ylab[tid];
        float epl = lse - yl;
        float tcp = __expf(yl - lse);

        float mx = tcp;
        #pragma unroll
        for (int off = 8; off; off >>= 1) mx = fmaxf(mx, __shfl_xor_sync(msk, mx, off));
        float e = __expf(tcp - mx), den = e;
        #pragma unroll
        for (int off = 8; off; off >>= 1) den += __shfl_xor_sync(msk, den, off);
        float tc = e / den;
        out[O_TC + b * M_ + tid] = tc;

        float mx2 = tc;
        #pragma unroll
        for (int off = 8; off; off >>= 1) mx2 = fmaxf(mx2, __shfl_xor_sync(msk, mx2, off));
        float e2 = __expf(tc - mx2), den2 = e2;
        #pragma unroll
        for (int off = 8; off; off >>= 1) den2 += __shfl_xor_sync(msk, den2, off);
        float t = e2 / den2;

        float x = my_wms;
        float conf  = x - x * t + log1pf(__expf(-x));
        float child = epl * x;
        #pragma unroll
        for (int off = 8; off; off >>= 1) {
            conf  += __shfl_xor_sync(msk, conf, off);
            child += __shfl_xor_sync(msk, child, off);
        }
        if (tid == 0) {
            g_part[b * 4 + 0] = child;
            g_part[b * 4 + 1] = conf;
            g_part[b * 4 + 2] = __logf(fin[16]) - slab_sh;
        }
    }
}

// ---------------------------------------------------------------------------
// Kernel D: final reduce.
// ---------------------------------------------------------------------------
__global__ __launch_bounds__(1024)
void k_final(float* __restrict__ out) {
    __shared__ float sm0[32], sm1[32], sm2[32];
    int t = threadIdx.x;
    const float4* gp = (const float4*)g_part;
    float4 r0 = gp[t];
    float4 r1 = gp[t + 1024];
    float4 r2 = gp[t + 2048];
    float4 r3 = gp[t + 3072];
    float a = (r0.x + r1.x) + (r2.x + r3.x);
    float b = (r0.y + r1.y) + (r2.y + r3.y);
    float c = (r0.z + r1.z) + (r2.z + r3.z);

    int lane = t & 31, wid = t >> 5;
    #pragma unroll
    for (int off = 16; off; off >>= 1) {
        a += __shfl_xor_sync(0xffffffffu, a, off);
        b += __shfl_xor_sync(0xffffffffu, b, off);
        c += __shfl_xor_sync(0xffffffffu, c, off);
    }
    if (lane == 0) { sm0[wid] = a; sm1[wid] = b; sm2[wid] = c; }
    __syncthreads();
    if (wid == 0) {
        float aa = sm0[lane], bb = sm1[lane], cc = sm2[lane];
        #pragma unroll
        for (int off = 16; off; off >>= 1) {
            aa += __shfl_xor_sync(0xffffffffu, aa, off);
            bb += __shfl_xor_sync(0xffffffffu, bb, off);
            cc += __shfl_xor_sync(0xffffffffu, cc, off);
        }
        if (lane == 0) {
            out[O_CHILD] = aa / (float)(B_ * M_);
            out[O_CONF]  = bb / (float)(B_ * M_);
            out[O_ENS]   = cc / (float)B_;
        }
    }
}

// ---------------------------------------------------------------------------
extern "C" void kernel_launch(void* const* d_in, const int* in_sizes, int n_in,
                              void* d_out, int out_size) {
    const float* x_in  = (const float*)d_in[0];
    const float* y     = (const float*)d_in[1];
    const int*   labs  = (const int*)  d_in[2];
    const float* memb  = (const float*)d_in[3];
    const float* w1    = (const float*)d_in[4];
    const float* b1    = (const float*)d_in[5];
    const float* w2    = (const float*)d_in[6];
    const float* b2    = (const float*)d_in[7];
    const float* w3    = (const float*)d_in[8];
    const float* b3    = (const float*)d_in[9];
    float* out = (float*)d_out;

    k_emb  <<<M_, 256>>>(memb, w2, b2);
    k_dummy<<<1, 32>>>();
    k_route<<<B_ / 16, 128>>>(x_in, w1, b1, w3, b3, out);
    k_main <<<B_, 256>>>(y, labs, out);        // profiled (pos 4)
    k_final<<<1, 1024>>>(out);
}

// round 5
// speedup vs baseline: 2.6386x; 1.0935x over previous
#include <cuda_runtime.h>
#include <math.h>
#include <stdint.h>

#define B_   4096
#define M_   16
#define C_   1000
#define EMB_ 100
#define EPAD 101
#define K_   1000
#define NL_  4

// output layout (tuple-order concat, fp32)
#define O_POST  0
#define O_CHILD 4096000
#define O_CONF  4096001
#define O_ENS   4096002
#define O_WMS   4096003
#define O_TC    4161539

// scratch
__device__ float g_emb[M_ * EMB_];
__device__ float g_wm [B_ * M_];
__device__ float g_pw [B_ * M_];
__device__ float g_wms[B_ * M_];
__device__ __align__(16) float g_part[B_ * 4];
__device__ unsigned int g_ctr;

__device__ __forceinline__ void cp16(uint32_t d, const void* s, int nbytes) {
    asm volatile("cp.async.cg.shared.global [%0], [%1], 16, %2;\n"
                 :: "r"(d), "l"(s), "r"(nbytes));
}

// ---------------------------------------------------------------------------
// Kernel A: emb[m][e] = relu(model_emb[m,:] . w2[e,:] + b2[e])
// grid (16, 13): one warp per (m, e).
// ---------------------------------------------------------------------------
__global__ void k_emb(const float* __restrict__ me, const float* __restrict__ w2,
                      const float* __restrict__ b2) {
    int m = blockIdx.x;
    int wid = threadIdx.x >> 5, lane = threadIdx.x & 31;
    int e = blockIdx.y * 8 + wid;
    if (e >= EMB_) return;
    const float* mer = me + m * K_;
    const float* w2r = w2 + e * K_;
    float acc = 0.f;
    #pragma unroll
    for (int i = 0; i < 32; i++) {
        int k = lane + (i << 5);
        if (k < K_) acc += mer[k] * w2r[k];
    }
    #pragma unroll
    for (int off = 16; off; off >>= 1)
        acc += __shfl_xor_sync(0xffffffffu, acc, off);
    if (lane == 0) g_emb[m * EMB_ + e] = fmaxf(acc + b2[e], 0.f);
}

// resets the completion counter used by k_main's fused final reduce
__global__ void k_dummy() { if (threadIdx.x == 0) g_ctr = 0u; }

// ---------------------------------------------------------------------------
// Kernel B (R3 version, known-good): routing. 256 blocks x 128 threads,
// 4 rows/warp, float4 FMAs, w1 double-buffered via cp.async.
// ---------------------------------------------------------------------------
#define CE_ 4

__global__ __launch_bounds__(128, 2)
void k_route(const float* __restrict__ x_in, const float* __restrict__ w1,
             const float* __restrict__ b1, const float* __restrict__ w3,
             const float* __restrict__ b3, float* __restrict__ out) {
    __shared__ __align__(16) float w_s[2][CE_ * 1024];   // 32 KB
    __shared__ float emb_s[M_ * EPAD];
    __shared__ float b1_s[EMB_];
    __shared__ float w3_s[M_ * M_];
    __shared__ float b3_s[M_];
    __shared__ float wtmp[16 * M_];

    int tid = threadIdx.x, wid = tid >> 5, lane = tid & 31;
    int base = blockIdx.x * 16;
    int m = lane & 15, h = lane >> 4;

    for (int i = tid; i < M_ * EMB_; i += 128) {
        int mm = i / EMB_, ee = i - mm * EMB_;
        emb_s[mm * EPAD + ee] = g_emb[i];
    }
    if (tid < EMB_) b1_s[tid] = b1[tid];
    for (int i = tid; i < M_ * M_; i += 128) w3_s[i] = w3[i];
    if (tid < M_) b3_s[tid] = b3[tid];

    // x preload: 4 rows, layout k = 4*lane + 128*i
    float4 xr[4][8];
    #pragma unroll
    for (int r = 0; r < 4; r++) {
        const float* xp = x_in + (size_t)(base + 4 * wid + r) * K_;
        #pragma unroll
        for (int i = 0; i < 8; i++) {
            int k = 4 * lane + 128 * i;
            xr[r][i] = (k < K_) ? *(const float4*)(xp + k)
                                : make_float4(0.f, 0.f, 0.f, 0.f);
        }
    }

    uint32_t wb0 = (uint32_t)__cvta_generic_to_shared(&w_s[0][0]);
    uint32_t wb1 = (uint32_t)__cvta_generic_to_shared(&w_s[1][0]);

    #define STAGE(c, wb) do {                                                  \
        int ec_ = (c) * CE_;                                                   \
        _Pragma("unroll")                                                      \
        for (int j_ = 0; j_ < 8; j_++) {                                       \
            int f4_ = j_ * 128 + tid;                                          \
            int el_ = f4_ >> 8, c4_ = f4_ & 255;                               \
            const float* src_ = w1 + (size_t)(ec_ + el_) * K_                  \
                                  + ((c4_ < 250) ? c4_ * 4 : 0);               \
            int nb_ = (c4_ < 250) ? 16 : 0;                                    \
            cp16((wb) + (uint32_t)((el_ * 1024 + c4_ * 4) * 4), src_, nb_);    \
        }                                                                      \
        asm volatile("cp.async.commit_group;\n");                              \
    } while (0)

    STAGE(0, wb0);

    float score0 = 0.f, score1 = 0.f, score2 = 0.f, score3 = 0.f;

    for (int c = 0; c < 25; c++) {
        asm volatile("cp.async.wait_group 0;\n");
        __syncthreads();
        if (c + 1 < 25) STAGE(c + 1, (c & 1) ? wb0 : wb1);
        const float* wbp = w_s[c & 1];

        #pragma unroll
        for (int ep = 0; ep < 2; ep++) {
            const float* w0p = wbp + (2 * ep) * 1024;
            const float* w1p = wbp + (2 * ep + 1) * 1024;
            float a00 = 0, a01 = 0, a02 = 0, a03 = 0;
            float a10 = 0, a11 = 0, a12 = 0, a13 = 0;
            #pragma unroll
            for (int i = 0; i < 8; i++) {
                int k = 4 * lane + 128 * i;
                float4 wa = *(const float4*)(w0p + k);
                float4 wc = *(const float4*)(w1p + k);
                float4 q;
                q = xr[0][i];
                a00 += wa.x*q.x + wa.y*q.y + wa.z*q.z + wa.w*q.w;
                a10 += wc.x*q.x + wc.y*q.y + wc.z*q.z + wc.w*q.w;
                q = xr[1][i];
                a01 += wa.x*q.x + wa.y*q.y + wa.z*q.z + wa.w*q.w;
                a11 += wc.x*q.x + wc.y*q.y + wc.z*q.z + wc.w*q.w;
                q = xr[2][i];
                a02 += wa.x*q.x + wa.y*q.y + wa.z*q.z + wa.w*q.w;
                a12 += wc.x*q.x + wc.y*q.y + wc.z*q.z + wc.w*q.w;
                q = xr[3][i];
                a03 += wa.x*q.x + wa.y*q.y + wa.z*q.z + wa.w*q.w;
                a13 += wc.x*q.x + wc.y*q.y + wc.z*q.z + wc.w*q.w;
            }
            #pragma unroll
            for (int off = 16; off; off >>= 1) {
                a00 += __shfl_xor_sync(0xffffffffu, a00, off);
                a01 += __shfl_xor_sync(0xffffffffu, a01, off);
                a02 += __shfl_xor_sync(0xffffffffu, a02, off);
                a03 += __shfl_xor_sync(0xffffffffu, a03, off);
                a10 += __shfl_xor_sync(0xffffffffu, a10, off);
                a11 += __shfl_xor_sync(0xffffffffu, a11, off);
                a12 += __shfl_xor_sync(0xffffffffu, a12, off);
                a13 += __shfl_xor_sync(0xffffffffu, a13, off);
            }
            int elh = c * CE_ + 2 * ep + h;
            float bias = b1_s[elh];
            float em   = emb_s[m * EPAD + elh];
            float f0 = fmaxf((h ? a10 : a00) + bias, 0.f);
            float f1 = fmaxf((h ? a11 : a01) + bias, 0.f);
            float f2 = fmaxf((h ? a12 : a02) + bias, 0.f);
            float f3 = fmaxf((h ? a13 : a03) + bias, 0.f);
            score0 += f0 * em; score1 += f1 * em;
            score2 += f2 * em; score3 += f3 * em;
        }
    }

    score0 += __shfl_xor_sync(0xffffffffu, score0, 16);
    score1 += __shfl_xor_sync(0xffffffffu, score1, 16);
    score2 += __shfl_xor_sync(0xffffffffu, score2, 16);
    score3 += __shfl_xor_sync(0xffffffffu, score3, 16);

    float acc0 = b3_s[m], acc1 = acc0, acc2 = acc0, acc3 = acc0;
    #pragma unroll
    for (int m2 = 0; m2 < M_; m2++) {
        float w = w3_s[m * M_ + m2];
        acc0 += w * __shfl_sync(0xffffffffu, score0, m2);
        acc1 += w * __shfl_sync(0xffffffffu, score1, m2);
        acc2 += w * __shfl_sync(0xffffffffu, score2, m2);
        acc3 += w * __shfl_sync(0xffffffffu, score3, m2);
    }
    float wg0 = fmaxf(acc0, 0.f) + log1pf(__expf(-fabsf(acc0)));
    float wg1 = fmaxf(acc1, 0.f) + log1pf(__expf(-fabsf(acc1)));
    float wg2 = fmaxf(acc2, 0.f) + log1pf(__expf(-fabsf(acc2)));
    float wg3 = fmaxf(acc3, 0.f) + log1pf(__expf(-fabsf(acc3)));

    float rs0 = wg0, rs1 = wg1, rs2 = wg2, rs3 = wg3;
    #pragma unroll
    for (int off = 8; off; off >>= 1) {
        rs0 += __shfl_xor_sync(0xffffffffu, rs0, off);
        rs1 += __shfl_xor_sync(0xffffffffu, rs1, off);
        rs2 += __shfl_xor_sync(0xffffffffu, rs2, off);
        rs3 += __shfl_xor_sync(0xffffffffu, rs3, off);
    }
    float wm0 = wg0 / fmaxf(rs0, 1e-12f);
    float wm1 = wg1 / fmaxf(rs1, 1e-12f);
    float wm2 = wg2 / fmaxf(rs2, 1e-12f);
    float wm3 = wg3 / fmaxf(rs3, 1e-12f);

    float mx0 = wm0, mx1 = wm1, mx2 = wm2, mx3 = wm3;
    #pragma unroll
    for (int off = 8; off; off >>= 1) {
        mx0 = fmaxf(mx0, __shfl_xor_sync(0xffffffffu, mx0, off));
        mx1 = fmaxf(mx1, __shfl_xor_sync(0xffffffffu, mx1, off));
        mx2 = fmaxf(mx2, __shfl_xor_sync(0xffffffffu, mx2, off));
        mx3 = fmaxf(mx3, __shfl_xor_sync(0xffffffffu, mx3, off));
    }
    float ex0 = __expf(wm0 - mx0), ex1 = __expf(wm1 - mx1);
    float ex2 = __expf(wm2 - mx2), ex3 = __expf(wm3 - mx3);
    float es0 = ex0, es1 = ex1, es2 = ex2, es3 = ex3;
    #pragma unroll
    for (int off = 8; off; off >>= 1) {
        es0 += __shfl_xor_sync(0xffffffffu, es0, off);
        es1 += __shfl_xor_sync(0xffffffffu, es1, off);
        es2 += __shfl_xor_sync(0xffffffffu, es2, off);
        es3 += __shfl_xor_sync(0xffffffffu, es3, off);
    }
    float wmsv[4] = {ex0 / es0, ex1 / es1, ex2 / es2, ex3 / es3};
    float wmv [4] = {wm0, wm1, wm2, wm3};

    if (lane < 16) {
        int lr = 4 * wid;
        #pragma unroll
        for (int r = 0; r < 4; r++) {
            int row = base + lr + r;
            g_wm [row * M_ + m] = wmv[r];
            g_wms[row * M_ + m] = wmsv[r];
            out[O_WMS + row * M_ + m] = wmsv[r];
            wtmp[(lr + r) * M_ + m] = wmv[r];
        }
    }
    __syncthreads();

    if (tid < 16) {
        float v[M_], pw[M_];
        #pragma unroll
        for (int j = 0; j < M_; j++) { v[j] = wtmp[tid * M_ + j]; pw[j] = 0.f; }
        float ssum = 0.f;
        #pragma unroll
        for (int it = 0; it < NL_; it++) {
            int bi = 0; float bv = -1.f;
            #pragma unroll
            for (int j = 0; j < M_; j++) if (v[j] > bv) { bv = v[j]; bi = j; }
            pw[bi] = bv; ssum += bv; v[bi] = -2.f;
        }
        float inv = 1.f / fmaxf(ssum, 1e-12f);
        int row2 = base + tid;
        #pragma unroll
        for (int j = 0; j < M_; j++) g_pw[row2 * M_ + j] = pw[j] * inv;
    }
}

// ---------------------------------------------------------------------------
// Kernel C: 262 MB streamer. One block per row. 4 chunks x 16 KB through
// 3 smem buffers (48.8 KB) -> 4 CTAs/SM, continuous cp.async issue.
// Final scalar reduce fused via atomic counter (last block).
// ---------------------------------------------------------------------------
__global__ __launch_bounds__(256, 4)
void k_main(const float* __restrict__ y, const int* __restrict__ labels,
            float* __restrict__ out) {
    __shared__ __align__(16) float4 yb_s[3][4][250];   // 48 KB
    __shared__ float wm_sh[M_], pw_sh[M_], ylab[M_];
    __shared__ float red[17][8];
    __shared__ float fin[17];
    __shared__ float slab_sh;
    __shared__ int islast;

    int b = blockIdx.x, tid = threadIdx.x;
    const float4* yb = (const float4*)(y + (size_t)b * (M_ * C_));

    #define KSTAGE(q, bq) do {                                                 \
        if (tid < 250) {                                                       \
            _Pragma("unroll")                                                  \
            for (int j_ = 0; j_ < 4; j_++)                                     \
                cp16((uint32_t)__cvta_generic_to_shared(&yb_s[bq][j_][tid]),   \
                     yb + ((q) * 4 + j_) * 250 + tid, 16);                     \
        }                                                                      \
        asm volatile("cp.async.commit_group;\n");                              \
    } while (0)

    KSTAGE(0, 0); KSTAGE(1, 1); KSTAGE(2, 2);

    float my_wms = 0.f;
    if (tid < M_) {
        wm_sh[tid] = g_wm[b * M_ + tid];
        pw_sh[tid] = g_pw[b * M_ + tid];
        my_wms = g_wms[b * M_ + tid];
    }

    int lab = labels[b];
    int labq = lab >> 2, labr = lab & 3;
    bool own = (tid == labq);

    float sume[M_];
    #pragma unroll
    for (int m = 0; m < M_; m++) sume[m] = 0.f;
    float sumS = 0.f;
    float s0 = 0, s1 = 0, s2 = 0, s3 = 0;
    float p0 = 0, p1 = 0, p2 = 0, p3 = 0;

    #define KCOMP(q, bq)                                                       \
        if (tid < 250) {                                                       \
            _Pragma("unroll")                                                  \
            for (int j_ = 0; j_ < 4; j_++) {                                   \
                int m_ = (q) * 4 + j_;                                         \
                float4 v = yb_s[bq][j_][tid];                                  \
                float wm = wm_sh[m_];                                          \
                s0 += wm * v.x; s1 += wm * v.y;                                \
                s2 += wm * v.z; s3 += wm * v.w;                                \
                float pw = pw_sh[m_];                                          \
                if (pw != 0.f) {                                               \
                    p0 += pw * v.x; p1 += pw * v.y;                            \
                    p2 += pw * v.z; p3 += pw * v.w;                            \
                }                                                              \
                sume[m_] += __expf(v.x) + __expf(v.y)                          \
                          + __expf(v.z) + __expf(v.w);                         \
                if (own) ylab[m_] = (labr == 0) ? v.x : (labr == 1) ? v.y :    \
                                    (labr == 2) ? v.z : v.w;                   \
            }                                                                  \
        }

    asm volatile("cp.async.wait_group 2;\n");
    __syncthreads();
    KCOMP(0, 0);
    __syncthreads();
    KSTAGE(3, 0);

    asm volatile("cp.async.wait_group 2;\n");
    __syncthreads();
    KCOMP(1, 1);

    asm volatile("cp.async.wait_group 1;\n");
    __syncthreads();
    KCOMP(2, 2);

    asm volatile("cp.async.wait_group 0;\n");
    __syncthreads();
    KCOMP(3, 0);

    if (tid < 250) {
        float4* ob = (float4*)(out + O_POST + (size_t)b * C_);
        ob[tid] = make_float4(p0, p1, p2, p3);
        sumS = __expf(s0) + __expf(s1) + __expf(s2) + __expf(s3);
        if (own) slab_sh = (labr == 0) ? s0 : (labr == 1) ? s1 :
                           (labr == 2) ? s2 : s3;
    }

    // block reduce 17 sums
    int lane = tid & 31, wid = tid >> 5;
    #pragma unroll
    for (int j = 0; j < 17; j++) {
        float v = (j < M_) ? sume[j] : sumS;
        #pragma unroll
        for (int off = 16; off; off >>= 1) v += __shfl_xor_sync(0xffffffffu, v, off);
        if (lane == 0) red[j][wid] = v;
    }
    __syncthreads();
    if (tid < 17) {
        float v = 0.f;
        #pragma unroll
        for (int w = 0; w < 8; w++) v += red[tid][w];
        fin[tid] = v;
    }
    __syncthreads();

    // lane-parallel epilogue (lanes 0-15 of warp 0)
    if (tid < 16) {
        const unsigned msk = 0xffffu;
        float lse = __logf(fin[tid]);
        float yl  = ylab[tid];
        float epl = lse - yl;
        float tcp = __expf(yl - lse);

        float mx = tcp;
        #pragma unroll
        for (int off = 8; off; off >>= 1) mx = fmaxf(mx, __shfl_xor_sync(msk, mx, off));
        float e = __expf(tcp - mx), den = e;
        #pragma unroll
        for (int off = 8; off; off >>= 1) den += __shfl_xor_sync(msk, den, off);
        float tc = e / den;
        out[O_TC + b * M_ + tid] = tc;

        float mx2 = tc;
        #pragma unroll
        for (int off = 8; off; off >>= 1) mx2 = fmaxf(mx2, __shfl_xor_sync(msk, mx2, off));
        float e2 = __expf(tc - mx2), den2 = e2;
        #pragma unroll
        for (int off = 8; off; off >>= 1) den2 += __shfl_xor_sync(msk, den2, off);
        float t = e2 / den2;

        float x = my_wms;
        float conf  = x - x * t + log1pf(__expf(-x));
        float child = epl * x;
        #pragma unroll
        for (int off = 8; off; off >>= 1) {
            conf  += __shfl_xor_sync(msk, conf, off);
            child += __shfl_xor_sync(msk, child, off);
        }
        if (tid == 0) {
            g_part[b * 4 + 0] = child;
            g_part[b * 4 + 1] = conf;
            g_part[b * 4 + 2] = __logf(fin[16]) - slab_sh;
        }
    }
    __syncthreads();

    // fused final reduce: last block to finish sums all partials
    if (tid == 0) {
        __threadfence();
        islast = (atomicAdd(&g_ctr, 1u) == (unsigned)(B_ - 1));
    }
    __syncthreads();
    if (islast) {
        __threadfence();
        float a = 0.f, bb = 0.f, cc = 0.f;
        const float4* gp = (const float4*)g_part;
        for (int i = tid; i < B_; i += 256) {
            float4 r = gp[i];
            a += r.x; bb += r.y; cc += r.z;
        }
        #pragma unroll
        for (int off = 16; off; off >>= 1) {
            a  += __shfl_xor_sync(0xffffffffu, a,  off);
            bb += __shfl_xor_sync(0xffffffffu, bb, off);
            cc += __shfl_xor_sync(0xffffffffu, cc, off);
        }
        if (lane == 0) { red[0][wid] = a; red[1][wid] = bb; red[2][wid] = cc; }
        __syncthreads();
        if (tid == 0) {
            float fa = 0.f, fb = 0.f, fc = 0.f;
            #pragma unroll
            for (int w = 0; w < 8; w++) { fa += red[0][w]; fb += red[1][w]; fc += red[2][w]; }
            out[O_CHILD] = fa / (float)(B_ * M_);
            out[O_CONF]  = fb / (float)(B_ * M_);
            out[O_ENS]   = fc / (float)B_;
        }
    }
}

// ---------------------------------------------------------------------------
extern "C" void kernel_launch(void* const* d_in, const int* in_sizes, int n_in,
                              void* d_out, int out_size) {
    const float* x_in  = (const float*)d_in[0];
    const float* y     = (const float*)d_in[1];
    const int*   labs  = (const int*)  d_in[2];
    const float* memb  = (const float*)d_in[3];
    const float* w1    = (const float*)d_in[4];
    const float* b1    = (const float*)d_in[5];
    const float* w2    = (const float*)d_in[6];
    const float* b2    = (const float*)d_in[7];
    const float* w3    = (const float*)d_in[8];
    const float* b3    = (const float*)d_in[9];
    float* out = (float*)d_out;

    k_emb  <<<dim3(M_, 13), 256>>>(memb, w2, b2);
    k_dummy<<<1, 32>>>();
    k_route<<<B_ / 16, 128>>>(x_in, w1, b1, w3, b3, out);
    k_main <<<B_, 256>>>(y, labs, out);        // profiled (pos 4)
}

// round 6
// speedup vs baseline: 2.7354x; 1.0367x over previous
#include <cuda_runtime.h>
#include <math.h>
#include <stdint.h>

#define B_   4096
#define M_   16
#define C_   1000
#define EMB_ 100
#define EPAD 101
#define K_   1000
#define NL_  4

// output layout (tuple-order concat, fp32)
#define O_POST  0
#define O_CHILD 4096000
#define O_CONF  4096001
#define O_ENS   4096002
#define O_WMS   4096003
#define O_TC    4161539

// scratch
__device__ float g_emb[M_ * EMB_];
__device__ float g_wm [B_ * M_];
__device__ float g_pw [B_ * M_];
__device__ float g_wms[B_ * M_];
__device__ __align__(16) float g_part[B_ * 4];
__device__ unsigned int g_ctr;

__device__ __forceinline__ void cp16(uint32_t d, const void* s, int nbytes) {
    asm volatile("cp.async.cg.shared.global [%0], [%1], 16, %2;\n"
                 :: "r"(d), "l"(s), "r"(nbytes));
}

// ---------------------------------------------------------------------------
// Kernel A: emb[m][e] = relu(model_emb[m,:] . w2[e,:] + b2[e])
// ---------------------------------------------------------------------------
__global__ void k_emb(const float* __restrict__ me, const float* __restrict__ w2,
                      const float* __restrict__ b2) {
    int m = blockIdx.x;
    int wid = threadIdx.x >> 5, lane = threadIdx.x & 31;
    int e = blockIdx.y * 8 + wid;
    if (e >= EMB_) return;
    const float* mer = me + m * K_;
    const float* w2r = w2 + e * K_;
    float acc = 0.f;
    #pragma unroll
    for (int i = 0; i < 32; i++) {
        int k = lane + (i << 5);
        if (k < K_) acc += mer[k] * w2r[k];
    }
    #pragma unroll
    for (int off = 16; off; off >>= 1)
        acc += __shfl_xor_sync(0xffffffffu, acc, off);
    if (lane == 0) g_emb[m * EMB_ + e] = fmaxf(acc + b2[e], 0.f);
}

// resets the completion counter used by k_main's fused final reduce
__global__ void k_dummy() { if (threadIdx.x == 0) g_ctr = 0u; }

// ---------------------------------------------------------------------------
// Kernel B (unchanged, known-good): routing. 256 blocks x 128 threads,
// 4 rows/warp, float4 FMAs, w1 double-buffered via cp.async.
// ---------------------------------------------------------------------------
#define CE_ 4

__global__ __launch_bounds__(128, 2)
void k_route(const float* __restrict__ x_in, const float* __restrict__ w1,
             const float* __restrict__ b1, const float* __restrict__ w3,
             const float* __restrict__ b3, float* __restrict__ out) {
    __shared__ __align__(16) float w_s[2][CE_ * 1024];   // 32 KB
    __shared__ float emb_s[M_ * EPAD];
    __shared__ float b1_s[EMB_];
    __shared__ float w3_s[M_ * M_];
    __shared__ float b3_s[M_];
    __shared__ float wtmp[16 * M_];

    int tid = threadIdx.x, wid = tid >> 5, lane = tid & 31;
    int base = blockIdx.x * 16;
    int m = lane & 15, h = lane >> 4;

    for (int i = tid; i < M_ * EMB_; i += 128) {
        int mm = i / EMB_, ee = i - mm * EMB_;
        emb_s[mm * EPAD + ee] = g_emb[i];
    }
    if (tid < EMB_) b1_s[tid] = b1[tid];
    for (int i = tid; i < M_ * M_; i += 128) w3_s[i] = w3[i];
    if (tid < M_) b3_s[tid] = b3[tid];

    // x preload: 4 rows, layout k = 4*lane + 128*i
    float4 xr[4][8];
    #pragma unroll
    for (int r = 0; r < 4; r++) {
        const float* xp = x_in + (size_t)(base + 4 * wid + r) * K_;
        #pragma unroll
        for (int i = 0; i < 8; i++) {
            int k = 4 * lane + 128 * i;
            xr[r][i] = (k < K_) ? *(const float4*)(xp + k)
                                : make_float4(0.f, 0.f, 0.f, 0.f);
        }
    }

    uint32_t wb0 = (uint32_t)__cvta_generic_to_shared(&w_s[0][0]);
    uint32_t wb1 = (uint32_t)__cvta_generic_to_shared(&w_s[1][0]);

    #define STAGE(c, wb) do {                                                  \
        int ec_ = (c) * CE_;                                                   \
        _Pragma("unroll")                                                      \
        for (int j_ = 0; j_ < 8; j_++) {                                       \
            int f4_ = j_ * 128 + tid;                                          \
            int el_ = f4_ >> 8, c4_ = f4_ & 255;                               \
            const float* src_ = w1 + (size_t)(ec_ + el_) * K_                  \
                                  + ((c4_ < 250) ? c4_ * 4 : 0);               \
            int nb_ = (c4_ < 250) ? 16 : 0;                                    \
            cp16((wb) + (uint32_t)((el_ * 1024 + c4_ * 4) * 4), src_, nb_);    \
        }                                                                      \
        asm volatile("cp.async.commit_group;\n");                              \
    } while (0)

    STAGE(0, wb0);

    float score0 = 0.f, score1 = 0.f, score2 = 0.f, score3 = 0.f;

    for (int c = 0; c < 25; c++) {
        asm volatile("cp.async.wait_group 0;\n");
        __syncthreads();
        if (c + 1 < 25) STAGE(c + 1, (c & 1) ? wb0 : wb1);
        const float* wbp = w_s[c & 1];

        #pragma unroll
        for (int ep = 0; ep < 2; ep++) {
            const float* w0p = wbp + (2 * ep) * 1024;
            const float* w1p = wbp + (2 * ep + 1) * 1024;
            float a00 = 0, a01 = 0, a02 = 0, a03 = 0;
            float a10 = 0, a11 = 0, a12 = 0, a13 = 0;
            #pragma unroll
            for (int i = 0; i < 8; i++) {
                int k = 4 * lane + 128 * i;
                float4 wa = *(const float4*)(w0p + k);
                float4 wc = *(const float4*)(w1p + k);
                float4 q;
                q = xr[0][i];
                a00 += wa.x*q.x + wa.y*q.y + wa.z*q.z + wa.w*q.w;
                a10 += wc.x*q.x + wc.y*q.y + wc.z*q.z + wc.w*q.w;
                q = xr[1][i];
                a01 += wa.x*q.x + wa.y*q.y + wa.z*q.z + wa.w*q.w;
                a11 += wc.x*q.x + wc.y*q.y + wc.z*q.z + wc.w*q.w;
                q = xr[2][i];
                a02 += wa.x*q.x + wa.y*q.y + wa.z*q.z + wa.w*q.w;
                a12 += wc.x*q.x + wc.y*q.y + wc.z*q.z + wc.w*q.w;
                q = xr[3][i];
                a03 += wa.x*q.x + wa.y*q.y + wa.z*q.z + wa.w*q.w;
                a13 += wc.x*q.x + wc.y*q.y + wc.z*q.z + wc.w*q.w;
            }
            #pragma unroll
            for (int off = 16; off; off >>= 1) {
                a00 += __shfl_xor_sync(0xffffffffu, a00, off);
                a01 += __shfl_xor_sync(0xffffffffu, a01, off);
                a02 += __shfl_xor_sync(0xffffffffu, a02, off);
                a03 += __shfl_xor_sync(0xffffffffu, a03, off);
                a10 += __shfl_xor_sync(0xffffffffu, a10, off);
                a11 += __shfl_xor_sync(0xffffffffu, a11, off);
                a12 += __shfl_xor_sync(0xffffffffu, a12, off);
                a13 += __shfl_xor_sync(0xffffffffu, a13, off);
            }
            int elh = c * CE_ + 2 * ep + h;
            float bias = b1_s[elh];
            float em   = emb_s[m * EPAD + elh];
            float f0 = fmaxf((h ? a10 : a00) + bias, 0.f);
            float f1 = fmaxf((h ? a11 : a01) + bias, 0.f);
            float f2 = fmaxf((h ? a12 : a02) + bias, 0.f);
            float f3 = fmaxf((h ? a13 : a03) + bias, 0.f);
            score0 += f0 * em; score1 += f1 * em;
            score2 += f2 * em; score3 += f3 * em;
        }
    }

    score0 += __shfl_xor_sync(0xffffffffu, score0, 16);
    score1 += __shfl_xor_sync(0xffffffffu, score1, 16);
    score2 += __shfl_xor_sync(0xffffffffu, score2, 16);
    score3 += __shfl_xor_sync(0xffffffffu, score3, 16);

    float acc0 = b3_s[m], acc1 = acc0, acc2 = acc0, acc3 = acc0;
    #pragma unroll
    for (int m2 = 0; m2 < M_; m2++) {
        float w = w3_s[m * M_ + m2];
        acc0 += w * __shfl_sync(0xffffffffu, score0, m2);
        acc1 += w * __shfl_sync(0xffffffffu, score1, m2);
        acc2 += w * __shfl_sync(0xffffffffu, score2, m2);
        acc3 += w * __shfl_sync(0xffffffffu, score3, m2);
    }
    float wg0 = fmaxf(acc0, 0.f) + log1pf(__expf(-fabsf(acc0)));
    float wg1 = fmaxf(acc1, 0.f) + log1pf(__expf(-fabsf(acc1)));
    float wg2 = fmaxf(acc2, 0.f) + log1pf(__expf(-fabsf(acc2)));
    float wg3 = fmaxf(acc3, 0.f) + log1pf(__expf(-fabsf(acc3)));

    float rs0 = wg0, rs1 = wg1, rs2 = wg2, rs3 = wg3;
    #pragma unroll
    for (int off = 8; off; off >>= 1) {
        rs0 += __shfl_xor_sync(0xffffffffu, rs0, off);
        rs1 += __shfl_xor_sync(0xffffffffu, rs1, off);
        rs2 += __shfl_xor_sync(0xffffffffu, rs2, off);
        rs3 += __shfl_xor_sync(0xffffffffu, rs3, off);
    }
    float wm0 = wg0 / fmaxf(rs0, 1e-12f);
    float wm1 = wg1 / fmaxf(rs1, 1e-12f);
    float wm2 = wg2 / fmaxf(rs2, 1e-12f);
    float wm3 = wg3 / fmaxf(rs3, 1e-12f);

    float mx0 = wm0, mx1 = wm1, mx2 = wm2, mx3 = wm3;
    #pragma unroll
    for (int off = 8; off; off >>= 1) {
        mx0 = fmaxf(mx0, __shfl_xor_sync(0xffffffffu, mx0, off));
        mx1 = fmaxf(mx1, __shfl_xor_sync(0xffffffffu, mx1, off));
        mx2 = fmaxf(mx2, __shfl_xor_sync(0xffffffffu, mx2, off));
        mx3 = fmaxf(mx3, __shfl_xor_sync(0xffffffffu, mx3, off));
    }
    float ex0 = __expf(wm0 - mx0), ex1 = __expf(wm1 - mx1);
    float ex2 = __expf(wm2 - mx2), ex3 = __expf(wm3 - mx3);
    float es0 = ex0, es1 = ex1, es2 = ex2, es3 = ex3;
    #pragma unroll
    for (int off = 8; off; off >>= 1) {
        es0 += __shfl_xor_sync(0xffffffffu, es0, off);
        es1 += __shfl_xor_sync(0xffffffffu, es1, off);
        es2 += __shfl_xor_sync(0xffffffffu, es2, off);
        es3 += __shfl_xor_sync(0xffffffffu, es3, off);
    }
    float wmsv[4] = {ex0 / es0, ex1 / es1, ex2 / es2, ex3 / es3};
    float wmv [4] = {wm0, wm1, wm2, wm3};

    if (lane < 16) {
        int lr = 4 * wid;
        #pragma unroll
        for (int r = 0; r < 4; r++) {
            int row = base + lr + r;
            g_wm [row * M_ + m] = wmv[r];
            g_wms[row * M_ + m] = wmsv[r];
            out[O_WMS + row * M_ + m] = wmsv[r];
            wtmp[(lr + r) * M_ + m] = wmv[r];
        }
    }
    __syncthreads();

    if (tid < 16) {
        float v[M_], pw[M_];
        #pragma unroll
        for (int j = 0; j < M_; j++) { v[j] = wtmp[tid * M_ + j]; pw[j] = 0.f; }
        float ssum = 0.f;
        #pragma unroll
        for (int it = 0; it < NL_; it++) {
            int bi = 0; float bv = -1.f;
            #pragma unroll
            for (int j = 0; j < M_; j++) if (v[j] > bv) { bv = v[j]; bi = j; }
            pw[bi] = bv; ssum += bv; v[bi] = -2.f;
        }
        float inv = 1.f / fmaxf(ssum, 1e-12f);
        int row2 = base + tid;
        #pragma unroll
        for (int j = 0; j < M_; j++) g_pw[row2 * M_ + j] = pw[j] * inv;
    }
}

// ---------------------------------------------------------------------------
// Kernel C: 262 MB streamer. One block per row. Models 0-11 staged via
// cp.async (48 KB smem, 3 groups); models 12-15 via LDG.128 into registers.
// Full 64 KB in flight per CTA, 4 CTAs/SM, no barriers between phases
// (each thread reads only the smem words it staged itself).
// Final scalar reduce fused via atomic counter (last block).
// ---------------------------------------------------------------------------
__global__ __launch_bounds__(256, 4)
void k_main(const float* __restrict__ y, const int* __restrict__ labels,
            float* __restrict__ out) {
    __shared__ __align__(16) float4 yb_s[12][250];   // 46.9 KB
    __shared__ float wm_sh[M_], pw_sh[M_], ylab[M_];
    __shared__ float red[17][8];
    __shared__ float fin[17];
    __shared__ float slab_sh;
    __shared__ int islast;

    int b = blockIdx.x, tid = threadIdx.x;
    const float4* yb = (const float4*)(y + (size_t)b * (M_ * C_));

    // stage models 0-11 (3 groups of 4) — all issued up front
    #define KSTAGE(q) do {                                                     \
        if (tid < 250) {                                                       \
            _Pragma("unroll")                                                  \
            for (int j_ = 0; j_ < 4; j_++)                                     \
                cp16((uint32_t)__cvta_generic_to_shared(                       \
                         &yb_s[(q) * 4 + j_][tid]),                            \
                     yb + ((q) * 4 + j_) * 250 + tid, 16);                     \
        }                                                                      \
        asm volatile("cp.async.commit_group;\n");                              \
    } while (0)

    KSTAGE(0); KSTAGE(1); KSTAGE(2);

    // models 12-15 via LDG (registers), issued immediately
    float4 va[4];
    if (tid < 250) {
        #pragma unroll
        for (int j = 0; j < 4; j++)
            va[j] = __ldcs(yb + (12 + j) * 250 + tid);
    }

    float my_wms = 0.f;
    if (tid < M_) {
        wm_sh[tid] = g_wm[b * M_ + tid];
        pw_sh[tid] = g_pw[b * M_ + tid];
        my_wms = g_wms[b * M_ + tid];
    }
    __syncthreads();   // publish wm_sh/pw_sh

    int lab = labels[b];
    int labq = lab >> 2, labr = lab & 3;
    bool own = (tid == labq);

    float sume[M_];
    #pragma unroll
    for (int m = 0; m < M_; m++) sume[m] = 0.f;
    float sumS = 0.f;
    float s0 = 0, s1 = 0, s2 = 0, s3 = 0;
    float p0 = 0, p1 = 0, p2 = 0, p3 = 0;

    #define KBODY(m_, v)                                                       \
        do {                                                                   \
            float wm = wm_sh[m_];                                              \
            s0 += wm * v.x; s1 += wm * v.y;                                    \
            s2 += wm * v.z; s3 += wm * v.w;                                    \
            float pw = pw_sh[m_];                                              \
            if (pw != 0.f) {                                                   \
                p0 += pw * v.x; p1 += pw * v.y;                                \
                p2 += pw * v.z; p3 += pw * v.w;                                \
            }                                                                  \
            sume[m_] += __expf(v.x) + __expf(v.y)                              \
                      + __expf(v.z) + __expf(v.w);                             \
            if (own) ylab[m_] = (labr == 0) ? v.x : (labr == 1) ? v.y :        \
                                (labr == 2) ? v.z : v.w;                       \
        } while (0)

    // register half first (models 12-15)
    if (tid < 250) {
        #pragma unroll
        for (int j = 0; j < 4; j++) KBODY(12 + j, va[j]);
    }

    // smem halves — no barriers: thread reads only its own staged words
    asm volatile("cp.async.wait_group 2;\n");
    if (tid < 250) {
        #pragma unroll
        for (int j = 0; j < 4; j++) { float4 v = yb_s[j][tid]; KBODY(j, v); }
    }
    asm volatile("cp.async.wait_group 1;\n");
    if (tid < 250) {
        #pragma unroll
        for (int j = 4; j < 8; j++) { float4 v = yb_s[j][tid]; KBODY(j, v); }
    }
    asm volatile("cp.async.wait_group 0;\n");
    if (tid < 250) {
        #pragma unroll
        for (int j = 8; j < 12; j++) { float4 v = yb_s[j][tid]; KBODY(j, v); }

        float4* ob = (float4*)(out + O_POST + (size_t)b * C_);
        __stcs(ob + tid, make_float4(p0, p1, p2, p3));
        sumS = __expf(s0) + __expf(s1) + __expf(s2) + __expf(s3);
        if (own) slab_sh = (labr == 0) ? s0 : (labr == 1) ? s1 :
                           (labr == 2) ? s2 : s3;
    }

    // block reduce 17 sums
    int lane = tid & 31, wid = tid >> 5;
    #pragma unroll
    for (int j = 0; j < 17; j++) {
        float v = (j < M_) ? sume[j] : sumS;
        #pragma unroll
        for (int off = 16; off; off >>= 1) v += __shfl_xor_sync(0xffffffffu, v, off);
        if (lane == 0) red[j][wid] = v;
    }
    __syncthreads();
    if (tid < 17) {
        float v = 0.f;
        #pragma unroll
        for (int w = 0; w < 8; w++) v += red[tid][w];
        fin[tid] = v;
    }
    __syncthreads();

    // lane-parallel epilogue (lanes 0-15 of warp 0)
    if (tid < 16) {
        const unsigned msk = 0xffffu;
        float lse = __logf(fin[tid]);
        float yl  = ylab[tid];
        float epl = lse - yl;
        float tcp = __expf(yl - lse);

        float mx = tcp;
        #pragma unroll
        for (int off = 8; off; off >>= 1) mx = fmaxf(mx, __shfl_xor_sync(msk, mx, off));
        float e = __expf(tcp - mx), den = e;
        #pragma unroll
        for (int off = 8; off; off >>= 1) den += __shfl_xor_sync(msk, den, off);
        float tc = e / den;
        out[O_TC + b * M_ + tid] = tc;

        float mx2 = tc;
        #pragma unroll
        for (int off = 8; off; off >>= 1) mx2 = fmaxf(mx2, __shfl_xor_sync(msk, mx2, off));
        float e2 = __expf(tc - mx2), den2 = e2;
        #pragma unroll
        for (int off = 8; off; off >>= 1) den2 += __shfl_xor_sync(msk, den2, off);
        float t = e2 / den2;

        float x = my_wms;
        float conf  = x - x * t + log1pf(__expf(-x));
        float child = epl * x;
        #pragma unroll
        for (int off = 8; off; off >>= 1) {
            conf  += __shfl_xor_sync(msk, conf, off);
            child += __shfl_xor_sync(msk, child, off);
        }
        if (tid == 0) {
            g_part[b * 4 + 0] = child;
            g_part[b * 4 + 1] = conf;
            g_part[b * 4 + 2] = __logf(fin[16]) - slab_sh;
        }
    }
    __syncthreads();

    // fused final reduce: last block to finish sums all partials
    if (tid == 0) {
        __threadfence();
        islast = (atomicAdd(&g_ctr, 1u) == (unsigned)(B_ - 1));
    }
    __syncthreads();
    if (islast) {
        __threadfence();
        float a = 0.f, bb = 0.f, cc = 0.f;
        const float4* gp = (const float4*)g_part;
        for (int i = tid; i < B_; i += 256) {
            float4 r = gp[i];
            a += r.x; bb += r.y; cc += r.z;
        }
        #pragma unroll
        for (int off = 16; off; off >>= 1) {
            a  += __shfl_xor_sync(0xffffffffu, a,  off);
            bb += __shfl_xor_sync(0xffffffffu, bb, off);
            cc += __shfl_xor_sync(0xffffffffu, cc, off);
        }
        if (lane == 0) { red[0][wid] = a; red[1][wid] = bb; red[2][wid] = cc; }
        __syncthreads();
        if (tid == 0) {
            float fa = 0.f, fb = 0.f, fc = 0.f;
            #pragma unroll
            for (int w = 0; w < 8; w++) { fa += red[0][w]; fb += red[1][w]; fc += red[2][w]; }
            out[O_CHILD] = fa / (float)(B_ * M_);
            out[O_CONF]  = fb / (float)(B_ * M_);
            out[O_ENS]   = fc / (float)B_;
        }
    }
}

// ---------------------------------------------------------------------------
extern "C" void kernel_launch(void* const* d_in, const int* in_sizes, int n_in,
                              void* d_out, int out_size) {
    const float* x_in  = (const float*)d_in[0];
    const float* y     = (const float*)d_in[1];
    const int*   labs  = (const int*)  d_in[2];
    const float* memb  = (const float*)d_in[3];
    const float* w1    = (const float*)d_in[4];
    const float* b1    = (const float*)d_in[5];
    const float* w2    = (const float*)d_in[6];
    const float* b2    = (const float*)d_in[7];
    const float* w3    = (const float*)d_in[8];
    const float* b3    = (const float*)d_in[9];
    float* out = (float*)d_out;

    k_emb  <<<dim3(M_, 13), 256>>>(memb, w2, b2);
    k_dummy<<<1, 32>>>();
    k_route<<<B_ / 16, 128>>>(x_in, w1, b1, w3, b3, out);
    k_main <<<B_, 256>>>(y, labs, out);        // profiled (pos 4)
}